// round 1
// baseline (speedup 1.0000x reference)
#include <cuda_runtime.h>
#include <cstdint>

// Problem constants
constexpr int NN = 10000;          // nodes
constexpr int F  = 256;            // feature dim (both in and out)
constexpr int NF = NN * F;         // 2,560,000 floats per matrix

// Scratch (allocation-free rule: __device__ globals)
__device__ float g_h[3 * NF];      // H1|H2|H3 = X@W1, X@W2, X@W3
__device__ float g_buf[4 * NF];    // [0]=acc (f1+f2+f3), [1]=t1, [2]=t2, [3]=t3

// ---------------------------------------------------------------------------
// zero kernel (float4 grid-stride)
// ---------------------------------------------------------------------------
__global__ void zero_kernel(float4* p, int n4) {
    int i = blockIdx.x * blockDim.x + threadIdx.x;
    int stride = gridDim.x * blockDim.x;
    for (; i < n4; i += stride) p[i] = make_float4(0.f, 0.f, 0.f, 0.f);
}

// ---------------------------------------------------------------------------
// Fused GEMM: H[which] = X @ W{which},  X: [M,256], W: [256,256] each.
// Grid: (12, ceil(M/64)). Block 256 threads, BM=BN=64, BK=32, 4x4 micro-tile.
// ---------------------------------------------------------------------------
#define BM 64
#define BN 64
#define BK 32
#define ASTRIDE 68   // padded to break STS bank conflicts; 68*4B % 16 == 0

__global__ __launch_bounds__(256) void gemm_kernel(
    const float* __restrict__ x,
    const float* __restrict__ W1,
    const float* __restrict__ W2,
    const float* __restrict__ W3,
    float* __restrict__ H, int M)
{
    __shared__ float As[BK][ASTRIDE];  // transposed: As[k][m]
    __shared__ float Bs[BK][BN];

    const int n0 = blockIdx.x * BN;            // 0..704 over concat width 768
    const int m0 = blockIdx.y * BM;
    const int which = n0 >> 8;                 // which W / H
    const float* W = (which == 0) ? W1 : (which == 1) ? W2 : W3;
    const int wc0 = n0 & 255;

    const int tid = threadIdx.x;
    const int tx = tid & 15;      // col group 0..15
    const int ty = tid >> 4;      // row group 0..15

    float acc[4][4];
#pragma unroll
    for (int i = 0; i < 4; i++)
#pragma unroll
        for (int j = 0; j < 4; j++) acc[i][j] = 0.f;

    for (int k0 = 0; k0 < 256; k0 += BK) {
        // --- load A tile (64 rows x 32 k), store transposed ---
#pragma unroll
        for (int l = 0; l < 2; l++) {
            int t   = tid + l * 256;          // 0..511 float4 slots
            int row = t >> 3;                 // 0..63
            int kc  = t & 7;                  // float4 index in k
            int gm  = m0 + row;
            float4 v = make_float4(0.f, 0.f, 0.f, 0.f);
            if (gm < M)
                v = *reinterpret_cast<const float4*>(x + (size_t)gm * 256 + k0 + kc * 4);
            As[kc * 4 + 0][row] = v.x;
            As[kc * 4 + 1][row] = v.y;
            As[kc * 4 + 2][row] = v.z;
            As[kc * 4 + 3][row] = v.w;
        }
        // --- load B tile (32 k x 64 cols) ---
#pragma unroll
        for (int l = 0; l < 2; l++) {
            int t  = tid + l * 256;
            int kr = t >> 4;                  // 0..31
            int nc = t & 15;                  // float4 col index
            float4 v = *reinterpret_cast<const float4*>(
                W + (size_t)(k0 + kr) * 256 + wc0 + nc * 4);
            *reinterpret_cast<float4*>(&Bs[kr][nc * 4]) = v;
        }
        __syncthreads();

#pragma unroll
        for (int k = 0; k < BK; k++) {
            float4 a = *reinterpret_cast<const float4*>(&As[k][ty * 4]);
            float4 b = *reinterpret_cast<const float4*>(&Bs[k][tx * 4]);
            acc[0][0] += a.x * b.x; acc[0][1] += a.x * b.y;
            acc[0][2] += a.x * b.z; acc[0][3] += a.x * b.w;
            acc[1][0] += a.y * b.x; acc[1][1] += a.y * b.y;
            acc[1][2] += a.y * b.z; acc[1][3] += a.y * b.w;
            acc[2][0] += a.z * b.x; acc[2][1] += a.z * b.y;
            acc[2][2] += a.z * b.z; acc[2][3] += a.z * b.w;
            acc[3][0] += a.w * b.x; acc[3][1] += a.w * b.y;
            acc[3][2] += a.w * b.z; acc[3][3] += a.w * b.w;
        }
        __syncthreads();
    }

    float* Hout = H + (size_t)which * NF;
#pragma unroll
    for (int i = 0; i < 4; i++) {
        int gm = m0 + ty * 4 + i;
        if (gm < M) {
            float4 v = make_float4(acc[i][0], acc[i][1], acc[i][2], acc[i][3]);
            *reinterpret_cast<float4*>(Hout + (size_t)gm * 256 + wc0 + tx * 4) = v;
        }
    }
}

// ---------------------------------------------------------------------------
// SpMM: out[dst[e]] += vals[e] * in[src[e]]   (warp per edge, NCH channels)
// Uses vector reduction red.global.add.v4.f32 (sm_90+) to quarter atomic count.
// ---------------------------------------------------------------------------
__device__ __forceinline__ void red4(float4* p, float a, float b, float c, float d) {
    asm volatile("red.global.add.v4.f32 [%0], {%1, %2, %3, %4};"
                 :: "l"(p), "f"(a), "f"(b), "f"(c), "f"(d) : "memory");
}

__device__ __forceinline__ void edge_ch(const float* __restrict__ in,
                                        float* __restrict__ out,
                                        int s, int d, float v, int lane)
{
    const float4* ip = reinterpret_cast<const float4*>(in + (size_t)s * 256);
    float4*       op = reinterpret_cast<float4*>(out + (size_t)d * 256);
    float4 a = ip[lane];
    float4 b = ip[lane + 32];
    red4(op + lane,      v * a.x, v * a.y, v * a.z, v * a.w);
    red4(op + lane + 32, v * b.x, v * b.y, v * b.z, v * b.w);
}

template <int NCH>
__global__ __launch_bounds__(256) void spmm_kernel(
    const float* __restrict__ vals,
    const int*   __restrict__ src,
    const int*   __restrict__ dst,
    int E,
    const float* __restrict__ i0, float* __restrict__ o0,
    const float* __restrict__ i1, float* __restrict__ o1,
    const float* __restrict__ i2, float* __restrict__ o2)
{
    int gtid = blockIdx.x * blockDim.x + threadIdx.x;
    int w = gtid >> 5;
    if (w >= E) return;
    int lane = gtid & 31;

    int   s = __ldg(&src[w]);
    int   d = __ldg(&dst[w]);
    float v = __ldg(&vals[w]);

    edge_ch(i0, o0, s, d, v, lane);
    if (NCH > 1) edge_ch(i1, o1, s, d, v, lane);
    if (NCH > 2) edge_ch(i2, o2, s, d, v, lane);
}

// ---------------------------------------------------------------------------
// Epilogue: out = relu(acc / 3)
// ---------------------------------------------------------------------------
__global__ void relu_kernel(const float4* __restrict__ acc, float4* __restrict__ out, int n4) {
    int i = blockIdx.x * blockDim.x + threadIdx.x;
    int stride = gridDim.x * blockDim.x;
    const float inv3 = 1.0f / 3.0f;
    for (; i < n4; i += stride) {
        float4 a = acc[i];
        out[i] = make_float4(fmaxf(a.x, 0.f) * inv3, fmaxf(a.y, 0.f) * inv3,
                             fmaxf(a.z, 0.f) * inv3, fmaxf(a.w, 0.f) * inv3);
    }
}

// ---------------------------------------------------------------------------
// Launch
// ---------------------------------------------------------------------------
extern "C" void kernel_launch(void* const* d_in, const int* in_sizes, int n_in,
                              void* d_out, int out_size)
{
    const float* x    = (const float*)d_in[0];
    const float* vals = (const float*)d_in[1];
    const float* W1   = (const float*)d_in[2];
    const float* W2   = (const float*)d_in[3];
    const float* W3   = (const float*)d_in[4];
    const int*   src  = (const int*)d_in[5];
    const int*   dst  = (const int*)d_in[6];

    const int M = in_sizes[0] / F;     // nodes (10000)
    const int E = in_sizes[1];         // edges (320000)

    float* h;   cudaGetSymbolAddress((void**)&h,   g_h);
    float* buf; cudaGetSymbolAddress((void**)&buf, g_buf);

    float* acc = buf;
    float* t1  = buf + (size_t)NF;
    float* t2  = buf + (size_t)2 * NF;
    float* t3  = buf + (size_t)3 * NF;

    // 1. zero accumulators (acc, t1, t2, t3)
    {
        int n4 = 4 * NF / 4;
        zero_kernel<<<4096, 256>>>(reinterpret_cast<float4*>(buf), n4);
    }

    // 2. H = X @ [W1|W2|W3]
    {
        dim3 grid(768 / BN, (M + BM - 1) / BM);
        gemm_kernel<<<grid, 256>>>(x, W1, W2, W3, h, M);
    }

    const int spmm_blocks = (E * 32 + 255) / 256;

    // 3. Pass A: f1 += A@h1 -> acc ; t1 = A@h2 ; t2 = A@h3
    spmm_kernel<3><<<spmm_blocks, 256>>>(vals, src, dst, E,
                                         h,               acc,
                                         h + (size_t)NF,  t1,
                                         h + (size_t)2*NF, t2);

    // 4. Pass B: f2 += A@t1 -> acc ; t3 = A@t2
    spmm_kernel<2><<<spmm_blocks, 256>>>(vals, src, dst, E,
                                         t1, acc,
                                         t2, t3,
                                         nullptr, nullptr);

    // 5. Pass C: f3 += A@t3 -> acc
    spmm_kernel<1><<<spmm_blocks, 256>>>(vals, src, dst, E,
                                         t3, acc,
                                         nullptr, nullptr,
                                         nullptr, nullptr);

    // 6. out = relu(acc / 3)
    relu_kernel<<<2500, 256>>>(reinterpret_cast<const float4*>(acc),
                               reinterpret_cast<float4*>(d_out), NF / 4);
}

// round 2
// speedup vs baseline: 1.7071x; 1.7071x over previous
#include <cuda_runtime.h>
#include <cstdint>

// Problem constants (fixed-shape problem)
constexpr int NN   = 10000;         // nodes
constexpr int F    = 256;           // feature dim
constexpr int NF   = NN * F;        // floats per matrix
constexpr int EMAX = 320000;        // edges

// Scratch (__device__ globals; no allocation allowed)
__device__ float g_h[3 * NF];       // H1|H2|H3 = X@W1, X@W2, X@W3
__device__ float g_buf[4 * NF];     // [0]=acc, [1]=t1, [2]=t2, [3]=t3
__device__ int   g_cnt[NN];
__device__ int   g_rowptr[NN + 1];
__device__ int   g_off[NN];
__device__ int   g_es[EMAX];        // CSR-ordered src
__device__ float g_ev[EMAX];        // CSR-ordered edge value

// ---------------------------------------------------------------------------
// CSR build: zero counts -> histogram -> scan -> scatter
// ---------------------------------------------------------------------------
__global__ void zero_cnt_kernel(int* cnt, int n) {
    int i = blockIdx.x * blockDim.x + threadIdx.x;
    if (i < n) cnt[i] = 0;
}

__global__ void hist_kernel(const int* __restrict__ dst, int* cnt, int E) {
    int i = blockIdx.x * blockDim.x + threadIdx.x;
    if (i < E) atomicAdd(&cnt[dst[i]], 1);
}

// single block, 1024 threads — exclusive scan into rowptr, running offsets into off
__global__ __launch_bounds__(1024) void scan_kernel(const int* __restrict__ cnt,
                                                    int* rowptr, int* off, int n) {
    __shared__ int sh[1024];
    __shared__ int carry_s;
    int tid = threadIdx.x;
    if (tid == 0) { carry_s = 0; rowptr[0] = 0; }
    __syncthreads();
    for (int base = 0; base < n; base += 1024) {
        int v = (base + tid < n) ? cnt[base + tid] : 0;
        sh[tid] = v;
        __syncthreads();
        for (int d = 1; d < 1024; d <<= 1) {
            int t = (tid >= d) ? sh[tid - d] : 0;
            __syncthreads();
            sh[tid] += t;
            __syncthreads();
        }
        int incl = sh[tid];
        int carry = carry_s;
        if (base + tid < n) {
            rowptr[base + tid + 1] = carry + incl;
            off[base + tid]        = carry + incl - v;
        }
        __syncthreads();
        if (tid == 1023) carry_s = carry + sh[1023];
        __syncthreads();
    }
}

__global__ void scatter_kernel(const int* __restrict__ src, const int* __restrict__ dst,
                               const float* __restrict__ vals,
                               int* off, int* es, float* ev, int E) {
    int i = blockIdx.x * blockDim.x + threadIdx.x;
    if (i < E) {
        int p = atomicAdd(&off[dst[i]], 1);
        es[p] = src[i];
        ev[p] = vals[i];
    }
}

// ---------------------------------------------------------------------------
// Fused GEMM: H = X @ [W1|W2|W3]  (same tiled SIMT GEMM as R1)
// ---------------------------------------------------------------------------
#define BM 64
#define BN 64
#define BK 32
#define ASTRIDE 68

__global__ __launch_bounds__(256) void gemm_kernel(
    const float* __restrict__ x,
    const float* __restrict__ W1,
    const float* __restrict__ W2,
    const float* __restrict__ W3,
    float* __restrict__ H, int M)
{
    __shared__ float As[BK][ASTRIDE];
    __shared__ float Bs[BK][BN];

    const int n0 = blockIdx.x * BN;
    const int m0 = blockIdx.y * BM;
    const int which = n0 >> 8;
    const float* W = (which == 0) ? W1 : (which == 1) ? W2 : W3;
    const int wc0 = n0 & 255;

    const int tid = threadIdx.x;
    const int tx = tid & 15;
    const int ty = tid >> 4;

    float acc[4][4];
#pragma unroll
    for (int i = 0; i < 4; i++)
#pragma unroll
        for (int j = 0; j < 4; j++) acc[i][j] = 0.f;

    for (int k0 = 0; k0 < 256; k0 += BK) {
#pragma unroll
        for (int l = 0; l < 2; l++) {
            int t = tid + l * 256;
            int row = t >> 3;
            int kc = t & 7;
            int gm = m0 + row;
            float4 v = make_float4(0.f, 0.f, 0.f, 0.f);
            if (gm < M)
                v = *reinterpret_cast<const float4*>(x + (size_t)gm * 256 + k0 + kc * 4);
            As[kc * 4 + 0][row] = v.x;
            As[kc * 4 + 1][row] = v.y;
            As[kc * 4 + 2][row] = v.z;
            As[kc * 4 + 3][row] = v.w;
        }
#pragma unroll
        for (int l = 0; l < 2; l++) {
            int t = tid + l * 256;
            int kr = t >> 4;
            int nc = t & 15;
            float4 v = *reinterpret_cast<const float4*>(
                W + (size_t)(k0 + kr) * 256 + wc0 + nc * 4);
            *reinterpret_cast<float4*>(&Bs[kr][nc * 4]) = v;
        }
        __syncthreads();

#pragma unroll
        for (int k = 0; k < BK; k++) {
            float4 a = *reinterpret_cast<const float4*>(&As[k][ty * 4]);
            float4 b = *reinterpret_cast<const float4*>(&Bs[k][tx * 4]);
            acc[0][0] += a.x * b.x; acc[0][1] += a.x * b.y;
            acc[0][2] += a.x * b.z; acc[0][3] += a.x * b.w;
            acc[1][0] += a.y * b.x; acc[1][1] += a.y * b.y;
            acc[1][2] += a.y * b.z; acc[1][3] += a.y * b.w;
            acc[2][0] += a.z * b.x; acc[2][1] += a.z * b.y;
            acc[2][2] += a.z * b.z; acc[2][3] += a.z * b.w;
            acc[3][0] += a.w * b.x; acc[3][1] += a.w * b.y;
            acc[3][2] += a.w * b.z; acc[3][3] += a.w * b.w;
        }
        __syncthreads();
    }

    float* Hout = H + (size_t)which * NF;
#pragma unroll
    for (int i = 0; i < 4; i++) {
        int gm = m0 + ty * 4 + i;
        if (gm < M) {
            float4 v = make_float4(acc[i][0], acc[i][1], acc[i][2], acc[i][3]);
            *reinterpret_cast<float4*>(Hout + (size_t)gm * 256 + wc0 + tx * 4) = v;
        }
    }
}

// ---------------------------------------------------------------------------
// Gather SpMM passes: warp per destination row, register accumulation.
// Each lane owns 8 floats of the 256-wide row (2 float4 at lane, lane+32).
// ---------------------------------------------------------------------------
__device__ __forceinline__ void fma4(float4& acc, float v, const float4& x) {
    acc.x = fmaf(v, x.x, acc.x);
    acc.y = fmaf(v, x.y, acc.y);
    acc.z = fmaf(v, x.z, acc.z);
    acc.w = fmaf(v, x.w, acc.w);
}

// Pass A: acc = A@h1, t1 = A@h2, t2 = A@h3 (3 channels share edge reads)
__global__ __launch_bounds__(256) void spmm_passA(
    const int* __restrict__ rowptr, const int* __restrict__ es,
    const float* __restrict__ ev,
    const float* __restrict__ h,
    float* __restrict__ acc, float* __restrict__ t1, float* __restrict__ t2, int n)
{
    int row = blockIdx.x * 8 + (threadIdx.x >> 5);
    if (row >= n) return;
    int lane = threadIdx.x & 31;
    int beg = rowptr[row], end = rowptr[row + 1];

    const float* h1 = h;
    const float* h2 = h + (size_t)NF;
    const float* h3 = h + (size_t)2 * NF;

    float4 a0 = {0,0,0,0}, b0 = {0,0,0,0};
    float4 a1 = {0,0,0,0}, b1 = {0,0,0,0};
    float4 a2 = {0,0,0,0}, b2 = {0,0,0,0};

#pragma unroll 2
    for (int e = beg; e < end; e++) {
        int   s = __ldg(es + e);
        float v = __ldg(ev + e);
        const float4* p1 = reinterpret_cast<const float4*>(h1 + (size_t)s * 256);
        const float4* p2 = reinterpret_cast<const float4*>(h2 + (size_t)s * 256);
        const float4* p3 = reinterpret_cast<const float4*>(h3 + (size_t)s * 256);
        float4 x0 = __ldg(p1 + lane), y0 = __ldg(p1 + lane + 32);
        float4 x1 = __ldg(p2 + lane), y1 = __ldg(p2 + lane + 32);
        float4 x2 = __ldg(p3 + lane), y2 = __ldg(p3 + lane + 32);
        fma4(a0, v, x0); fma4(b0, v, y0);
        fma4(a1, v, x1); fma4(b1, v, y1);
        fma4(a2, v, x2); fma4(b2, v, y2);
    }

    float4* oa = reinterpret_cast<float4*>(acc + (size_t)row * 256);
    float4* o1 = reinterpret_cast<float4*>(t1  + (size_t)row * 256);
    float4* o2 = reinterpret_cast<float4*>(t2  + (size_t)row * 256);
    oa[lane] = a0; oa[lane + 32] = b0;
    o1[lane] = a1; o1[lane + 32] = b1;
    o2[lane] = a2; o2[lane + 32] = b2;
}

// Pass B: acc += A@t1, t3 = A@t2
__global__ __launch_bounds__(256) void spmm_passB(
    const int* __restrict__ rowptr, const int* __restrict__ es,
    const float* __restrict__ ev,
    const float* __restrict__ t1, const float* __restrict__ t2,
    float* __restrict__ acc, float* __restrict__ t3, int n)
{
    int row = blockIdx.x * 8 + (threadIdx.x >> 5);
    if (row >= n) return;
    int lane = threadIdx.x & 31;
    int beg = rowptr[row], end = rowptr[row + 1];

    float4 a0 = {0,0,0,0}, b0 = {0,0,0,0};
    float4 a1 = {0,0,0,0}, b1 = {0,0,0,0};

#pragma unroll 2
    for (int e = beg; e < end; e++) {
        int   s = __ldg(es + e);
        float v = __ldg(ev + e);
        const float4* p1 = reinterpret_cast<const float4*>(t1 + (size_t)s * 256);
        const float4* p2 = reinterpret_cast<const float4*>(t2 + (size_t)s * 256);
        float4 x0 = __ldg(p1 + lane), y0 = __ldg(p1 + lane + 32);
        float4 x1 = __ldg(p2 + lane), y1 = __ldg(p2 + lane + 32);
        fma4(a0, v, x0); fma4(b0, v, y0);
        fma4(a1, v, x1); fma4(b1, v, y1);
    }

    float4* oa = reinterpret_cast<float4*>(acc + (size_t)row * 256);
    float4* o3 = reinterpret_cast<float4*>(t3  + (size_t)row * 256);
    float4 ca = oa[lane], cb = oa[lane + 32];
    ca.x += a0.x; ca.y += a0.y; ca.z += a0.z; ca.w += a0.w;
    cb.x += b0.x; cb.y += b0.y; cb.z += b0.z; cb.w += b0.w;
    oa[lane] = ca; oa[lane + 32] = cb;
    o3[lane] = a1; o3[lane + 32] = b1;
}

// Pass C: out = relu((acc + A@t3) / 3)  — fused epilogue, writes d_out
__global__ __launch_bounds__(256) void spmm_passC(
    const int* __restrict__ rowptr, const int* __restrict__ es,
    const float* __restrict__ ev,
    const float* __restrict__ t3, const float* __restrict__ acc,
    float* __restrict__ out, int n)
{
    int row = blockIdx.x * 8 + (threadIdx.x >> 5);
    if (row >= n) return;
    int lane = threadIdx.x & 31;
    int beg = rowptr[row], end = rowptr[row + 1];

    float4 a0 = {0,0,0,0}, b0 = {0,0,0,0};

#pragma unroll 2
    for (int e = beg; e < end; e++) {
        int   s = __ldg(es + e);
        float v = __ldg(ev + e);
        const float4* p = reinterpret_cast<const float4*>(t3 + (size_t)s * 256);
        float4 x0 = __ldg(p + lane), y0 = __ldg(p + lane + 32);
        fma4(a0, v, x0); fma4(b0, v, y0);
    }

    const float4* ia = reinterpret_cast<const float4*>(acc + (size_t)row * 256);
    float4* op = reinterpret_cast<float4*>(out + (size_t)row * 256);
    float4 ca = ia[lane], cb = ia[lane + 32];
    const float inv3 = 1.0f / 3.0f;
    float4 r0, r1;
    r0.x = fmaxf((ca.x + a0.x), 0.f) * inv3;
    r0.y = fmaxf((ca.y + a0.y), 0.f) * inv3;
    r0.z = fmaxf((ca.z + a0.z), 0.f) * inv3;
    r0.w = fmaxf((ca.w + a0.w), 0.f) * inv3;
    r1.x = fmaxf((cb.x + b0.x), 0.f) * inv3;
    r1.y = fmaxf((cb.y + b0.y), 0.f) * inv3;
    r1.z = fmaxf((cb.z + b0.z), 0.f) * inv3;
    r1.w = fmaxf((cb.w + b0.w), 0.f) * inv3;
    op[lane] = r0; op[lane + 32] = r1;
}

// ---------------------------------------------------------------------------
// Launch
// ---------------------------------------------------------------------------
extern "C" void kernel_launch(void* const* d_in, const int* in_sizes, int n_in,
                              void* d_out, int out_size)
{
    const float* x    = (const float*)d_in[0];
    const float* vals = (const float*)d_in[1];
    const float* W1   = (const float*)d_in[2];
    const float* W2   = (const float*)d_in[3];
    const float* W3   = (const float*)d_in[4];
    const int*   src  = (const int*)d_in[5];
    const int*   dst  = (const int*)d_in[6];

    const int M = in_sizes[0] / F;   // nodes
    const int E = in_sizes[1];       // edges

    float* h;      cudaGetSymbolAddress((void**)&h,      g_h);
    float* buf;    cudaGetSymbolAddress((void**)&buf,    g_buf);
    int*   cnt;    cudaGetSymbolAddress((void**)&cnt,    g_cnt);
    int*   rowptr; cudaGetSymbolAddress((void**)&rowptr, g_rowptr);
    int*   off;    cudaGetSymbolAddress((void**)&off,    g_off);
    int*   es;     cudaGetSymbolAddress((void**)&es,     g_es);
    float* ev;     cudaGetSymbolAddress((void**)&ev,     g_ev);

    float* acc = buf;
    float* t1  = buf + (size_t)NF;
    float* t2  = buf + (size_t)2 * NF;
    float* t3  = buf + (size_t)3 * NF;

    // --- CSR build ---
    zero_cnt_kernel<<<(M + 255) / 256, 256>>>(cnt, M);
    hist_kernel<<<(E + 255) / 256, 256>>>(dst, cnt, E);
    scan_kernel<<<1, 1024>>>(cnt, rowptr, off, M);
    scatter_kernel<<<(E + 255) / 256, 256>>>(src, dst, vals, off, es, ev, E);

    // --- GEMM: H = X @ [W1|W2|W3] ---
    {
        dim3 grid(768 / BN, (M + BM - 1) / BM);
        gemm_kernel<<<grid, 256>>>(x, W1, W2, W3, h, M);
    }

    // --- SpMM chain (gather, no atomics) ---
    const int rows_blocks = (M + 7) / 8;
    spmm_passA<<<rows_blocks, 256>>>(rowptr, es, ev, h, acc, t1, t2, M);
    spmm_passB<<<rows_blocks, 256>>>(rowptr, es, ev, t1, t2, acc, t3, M);
    spmm_passC<<<rows_blocks, 256>>>(rowptr, es, ev, t3, acc, (float*)d_out, M);
}

// round 4
// speedup vs baseline: 2.3428x; 1.3723x over previous
#include <cuda_runtime.h>
#include <cuda_fp16.h>
#include <cstdint>

// Problem constants (fixed-shape problem)
constexpr int NN   = 10000;         // nodes
constexpr int F    = 256;           // feature dim
constexpr int NF   = NN * F;        // elems per matrix
constexpr int EMAX = 320000;        // edges

// Scratch (__device__ globals; no allocation allowed)
__device__ __half g_h[3 * NF];      // H1|H2|H3 = fp16(X@W1), fp16(X@W2), fp16(X@W3)
__device__ __half g_s[2 * NF];      // s1, s2 intermediates (fp16)
__device__ int    g_cnt[NN];
__device__ int    g_rowptr[NN + 1];
__device__ int    g_off[NN];
__device__ int    g_es[EMAX];       // CSR-ordered src
__device__ float  g_ev[EMAX];       // CSR-ordered edge value

// ---------------------------------------------------------------------------
// fp16 helpers
// ---------------------------------------------------------------------------
__device__ __forceinline__ float2 h2f(unsigned u) {
    __half2 h = *reinterpret_cast<__half2*>(&u);
    return __half22float2(h);
}
__device__ __forceinline__ unsigned f2h(float a, float b) {
    __half2 h = __floats2half2_rn(a, b);
    return *reinterpret_cast<unsigned*>(&h);
}

// ---------------------------------------------------------------------------
// CSR build: zero counts -> histogram -> scan -> scatter
// ---------------------------------------------------------------------------
__global__ void zero_cnt_kernel(int* cnt, int n) {
    int i = blockIdx.x * blockDim.x + threadIdx.x;
    if (i < n) cnt[i] = 0;
}

__global__ void hist_kernel(const int* __restrict__ dst, int* cnt, int E) {
    int i = blockIdx.x * blockDim.x + threadIdx.x;
    if (i < E) atomicAdd(&cnt[dst[i]], 1);
}

// single block, 1024 threads — exclusive scan into rowptr, running offsets into off
__global__ __launch_bounds__(1024) void scan_kernel(const int* __restrict__ cnt,
                                                    int* rowptr, int* off, int n) {
    __shared__ int sh[1024];
    __shared__ int carry_s;
    int tid = threadIdx.x;
    if (tid == 0) { carry_s = 0; rowptr[0] = 0; }
    __syncthreads();
    for (int base = 0; base < n; base += 1024) {
        int v = (base + tid < n) ? cnt[base + tid] : 0;
        sh[tid] = v;
        __syncthreads();
        for (int d = 1; d < 1024; d <<= 1) {
            int t = (tid >= d) ? sh[tid - d] : 0;
            __syncthreads();
            sh[tid] += t;
            __syncthreads();
        }
        int incl = sh[tid];
        int carry = carry_s;
        if (base + tid < n) {
            rowptr[base + tid + 1] = carry + incl;
            off[base + tid]        = carry + incl - v;
        }
        __syncthreads();
        if (tid == 1023) carry_s = carry + sh[1023];
        __syncthreads();
    }
}

__global__ void scatter_kernel(const int* __restrict__ src, const int* __restrict__ dst,
                               const float* __restrict__ vals,
                               int* off, int* es, float* ev, int E) {
    int i = blockIdx.x * blockDim.x + threadIdx.x;
    if (i < E) {
        int p = atomicAdd(&off[dst[i]], 1);
        es[p] = src[i];
        ev[p] = vals[i];
    }
}

// ---------------------------------------------------------------------------
// Fused GEMM: H = fp16(X @ [W1|W2|W3]),  128x128x16 tiles, 8x8 micro-tile.
// Grid: (6, ceil(M/128)), block 256.
// ---------------------------------------------------------------------------
#define BM 128
#define BN 128
#define BK 16
#define APAD 132

__global__ __launch_bounds__(256) void gemm_kernel(
    const float* __restrict__ x,
    const float* __restrict__ W1,
    const float* __restrict__ W2,
    const float* __restrict__ W3,
    __half* __restrict__ H, int M)
{
    __shared__ float As[BK][APAD];   // transposed: As[k][m]
    __shared__ float Bs[BK][BN];

    const int n0 = blockIdx.x * BN;            // over concat width 768
    const int m0 = blockIdx.y * BM;
    const int which = n0 >> 8;
    const float* W = (which == 0) ? W1 : (which == 1) ? W2 : W3;
    const int wc0 = n0 & 255;

    const int tid = threadIdx.x;
    const int tx = tid & 15;      // 0..15 -> 8 cols each
    const int ty = tid >> 4;      // 0..15 -> 8 rows each

    float acc[8][8];
#pragma unroll
    for (int i = 0; i < 8; i++)
#pragma unroll
        for (int j = 0; j < 8; j++) acc[i][j] = 0.f;

    for (int k0 = 0; k0 < 256; k0 += BK) {
        // load A tile: 128 rows x 16 k = 512 float4 slots, transposed store
#pragma unroll
        for (int l = 0; l < 2; l++) {
            int s   = tid * 2 + l;            // 0..511
            int row = s >> 2;                 // 0..127
            int kc  = s & 3;                  // float4 index within 16 k
            int gm  = m0 + row;
            float4 v = make_float4(0.f, 0.f, 0.f, 0.f);
            if (gm < M)
                v = *reinterpret_cast<const float4*>(x + (size_t)gm * 256 + k0 + kc * 4);
            As[kc * 4 + 0][row] = v.x;
            As[kc * 4 + 1][row] = v.y;
            As[kc * 4 + 2][row] = v.z;
            As[kc * 4 + 3][row] = v.w;
        }
        // load B tile: 16 k x 128 n = 512 float4 slots
#pragma unroll
        for (int l = 0; l < 2; l++) {
            int s  = tid * 2 + l;
            int kr = s >> 5;                  // 0..15
            int nc = s & 31;                  // float4 col index
            float4 v = *reinterpret_cast<const float4*>(
                W + (size_t)(k0 + kr) * 256 + wc0 + nc * 4);
            *reinterpret_cast<float4*>(&Bs[kr][nc * 4]) = v;
        }
        __syncthreads();

#pragma unroll
        for (int k = 0; k < BK; k++) {
            float a[8], b[8];
            *reinterpret_cast<float4*>(&a[0]) = *reinterpret_cast<const float4*>(&As[k][ty * 8]);
            *reinterpret_cast<float4*>(&a[4]) = *reinterpret_cast<const float4*>(&As[k][ty * 8 + 4]);
            *reinterpret_cast<float4*>(&b[0]) = *reinterpret_cast<const float4*>(&Bs[k][tx * 8]);
            *reinterpret_cast<float4*>(&b[4]) = *reinterpret_cast<const float4*>(&Bs[k][tx * 8 + 4]);
#pragma unroll
            for (int i = 0; i < 8; i++)
#pragma unroll
                for (int j = 0; j < 8; j++)
                    acc[i][j] = fmaf(a[i], b[j], acc[i][j]);
        }
        __syncthreads();
    }

    __half* Hout = H + (size_t)which * NF;
#pragma unroll
    for (int i = 0; i < 8; i++) {
        int gm = m0 + ty * 8 + i;
        if (gm < M) {
            uint4 o;
            o.x = f2h(acc[i][0], acc[i][1]);
            o.y = f2h(acc[i][2], acc[i][3]);
            o.z = f2h(acc[i][4], acc[i][5]);
            o.w = f2h(acc[i][6], acc[i][7]);
            *reinterpret_cast<uint4*>(Hout + (size_t)gm * 256 + wc0 + tx * 8) = o;
        }
    }
}

// ---------------------------------------------------------------------------
// Horner SpMM pass: r = A @ gin  (+ addin[row]); store fp16 (or relu(r/3) fp32).
// Warp per destination row. Lane owns elems [4l,4l+4) and [128+4l,128+4l+4).
// fp16 row = 512B: two LDG.64 per lane, fully coalesced.
// ---------------------------------------------------------------------------
template <bool ADD, bool FINAL>
__global__ __launch_bounds__(256) void spmm_pass(
    const int* __restrict__ rowptr, const int* __restrict__ es,
    const float* __restrict__ ev,
    const __half* __restrict__ gin,
    const __half* __restrict__ addin,
    __half* __restrict__ hout,
    float* __restrict__ fout, int n)
{
    int row = blockIdx.x * 8 + (threadIdx.x >> 5);
    if (row >= n) return;
    int lane = threadIdx.x & 31;
    int beg = rowptr[row], end = rowptr[row + 1];

    float4 a = {0,0,0,0}, b = {0,0,0,0};

#pragma unroll 2
    for (int e = beg; e < end; e++) {
        int   s = __ldg(es + e);
        float v = __ldg(ev + e);
        const uint2* p = reinterpret_cast<const uint2*>(gin + (size_t)s * 256);
        uint2 u0 = __ldg(p + lane);
        uint2 u1 = __ldg(p + lane + 32);
        float2 f0 = h2f(u0.x), f1 = h2f(u0.y);
        float2 f2 = h2f(u1.x), f3 = h2f(u1.y);
        a.x = fmaf(v, f0.x, a.x); a.y = fmaf(v, f0.y, a.y);
        a.z = fmaf(v, f1.x, a.z); a.w = fmaf(v, f1.y, a.w);
        b.x = fmaf(v, f2.x, b.x); b.y = fmaf(v, f2.y, b.y);
        b.z = fmaf(v, f3.x, b.z); b.w = fmaf(v, f3.y, b.w);
    }

    if (ADD) {
        const uint2* q = reinterpret_cast<const uint2*>(addin + (size_t)row * 256);
        uint2 u0 = __ldg(q + lane);
        uint2 u1 = __ldg(q + lane + 32);
        float2 f0 = h2f(u0.x), f1 = h2f(u0.y);
        float2 f2 = h2f(u1.x), f3 = h2f(u1.y);
        a.x += f0.x; a.y += f0.y; a.z += f1.x; a.w += f1.y;
        b.x += f2.x; b.y += f2.y; b.z += f3.x; b.w += f3.y;
    }

    if (FINAL) {
        const float inv3 = 1.0f / 3.0f;
        float4 r0, r1;
        r0.x = fmaxf(a.x, 0.f) * inv3; r0.y = fmaxf(a.y, 0.f) * inv3;
        r0.z = fmaxf(a.z, 0.f) * inv3; r0.w = fmaxf(a.w, 0.f) * inv3;
        r1.x = fmaxf(b.x, 0.f) * inv3; r1.y = fmaxf(b.y, 0.f) * inv3;
        r1.z = fmaxf(b.z, 0.f) * inv3; r1.w = fmaxf(b.w, 0.f) * inv3;
        float4* op = reinterpret_cast<float4*>(fout + (size_t)row * 256);
        op[lane] = r0; op[lane + 32] = r1;
    } else {
        uint2 o0, o1;
        o0.x = f2h(a.x, a.y); o0.y = f2h(a.z, a.w);
        o1.x = f2h(b.x, b.y); o1.y = f2h(b.z, b.w);
        uint2* op = reinterpret_cast<uint2*>(hout + (size_t)row * 256);
        op[lane] = o0; op[lane + 32] = o1;
    }
}

// ---------------------------------------------------------------------------
// Launch
// ---------------------------------------------------------------------------
extern "C" void kernel_launch(void* const* d_in, const int* in_sizes, int n_in,
                              void* d_out, int out_size)
{
    const float* x    = (const float*)d_in[0];
    const float* vals = (const float*)d_in[1];
    const float* W1   = (const float*)d_in[2];
    const float* W2   = (const float*)d_in[3];
    const float* W3   = (const float*)d_in[4];
    const int*   src  = (const int*)d_in[5];
    const int*   dst  = (const int*)d_in[6];

    const int M = in_sizes[0] / F;   // nodes
    const int E = in_sizes[1];       // edges

    __half* h;     cudaGetSymbolAddress((void**)&h,      g_h);
    __half* sbuf;  cudaGetSymbolAddress((void**)&sbuf,   g_s);
    int*   cnt;    cudaGetSymbolAddress((void**)&cnt,    g_cnt);
    int*   rowptr; cudaGetSymbolAddress((void**)&rowptr, g_rowptr);
    int*   off;    cudaGetSymbolAddress((void**)&off,    g_off);
    int*   es;     cudaGetSymbolAddress((void**)&es,     g_es);
    float* ev;     cudaGetSymbolAddress((void**)&ev,     g_ev);

    __half* h1 = h;
    __half* h2 = h + (size_t)NF;
    __half* h3 = h + (size_t)2 * NF;
    __half* s1 = sbuf;
    __half* s2 = sbuf + (size_t)NF;

    // --- CSR build ---
    zero_cnt_kernel<<<(M + 255) / 256, 256>>>(cnt, M);
    hist_kernel<<<(E + 255) / 256, 256>>>(dst, cnt, E);
    scan_kernel<<<1, 1024>>>(cnt, rowptr, off, M);
    scatter_kernel<<<(E + 255) / 256, 256>>>(src, dst, vals, off, es, ev, E);

    // --- GEMM: H = fp16(X @ [W1|W2|W3]) ---
    {
        dim3 grid(768 / BN, (M + BM - 1) / BM);
        gemm_kernel<<<grid, 256>>>(x, W1, W2, W3, h, M);
    }

    // --- Horner SpMM chain: out = relu( A@(h1 + A@(h2 + A@h3)) / 3 ) ---
    const int rows_blocks = (M + 7) / 8;
    // s1 = A@h3 + h2
    spmm_pass<true, false><<<rows_blocks, 256>>>(rowptr, es, ev, h3, h2, s1, nullptr, M);
    // s2 = A@s1 + h1
    spmm_pass<true, false><<<rows_blocks, 256>>>(rowptr, es, ev, s1, h1, s2, nullptr, M);
    // out = relu(A@s2 / 3)
    spmm_pass<false, true><<<rows_blocks, 256>>>(rowptr, es, ev, s2, nullptr, nullptr,
                                                 (float*)d_out, M);
}

// round 7
// speedup vs baseline: 4.1930x; 1.7897x over previous
#include <cuda_runtime.h>
#include <cuda_fp16.h>
#include <mma.h>
#include <cstdint>

using namespace nvcuda;

// Problem constants (fixed-shape problem)
constexpr int NN   = 10000;         // nodes
constexpr int F    = 256;           // feature dim
constexpr int NF   = NN * F;        // elems per matrix
constexpr int EMAX = 320000;        // edges
constexpr int WSZ  = 65536;         // 256*256 per W

// Scratch (__device__ globals; no allocation allowed)
__device__ __half g_h[3 * NF];      // H1|H2|H3 = fp16(X@W1..3)
__device__ __half g_s[2 * NF];      // s1, s2 intermediates (fp16)
__device__ __half g_xh[NF];         // fp16 X
__device__ __half g_wh[3 * WSZ];    // fp16 W1|W2|W3 (each row-major [256][256])
__device__ int    g_cnt[NN];
__device__ int    g_rowptr[NN + 1];
__device__ int    g_off[NN];
__device__ int    g_es[EMAX];       // CSR-ordered src
__device__ float  g_ev[EMAX];       // CSR-ordered edge value

// ---------------------------------------------------------------------------
// fp16 helpers
// ---------------------------------------------------------------------------
__device__ __forceinline__ float2 h2f(unsigned u) {
    __half2 h = *reinterpret_cast<__half2*>(&u);
    return __half22float2(h);
}
__device__ __forceinline__ unsigned f2h(float a, float b) {
    __half2 h = __floats2half2_rn(a, b);
    return *reinterpret_cast<unsigned*>(&h);
}

// ---------------------------------------------------------------------------
// fp32 -> fp16 convert (vectorized)
// ---------------------------------------------------------------------------
__global__ void conv_kernel(const float4* __restrict__ in, uint2* __restrict__ out, int n4) {
    int i = blockIdx.x * blockDim.x + threadIdx.x;
    int stride = gridDim.x * blockDim.x;
    for (; i < n4; i += stride) {
        float4 v = in[i];
        uint2 o;
        o.x = f2h(v.x, v.y);
        o.y = f2h(v.z, v.w);
        out[i] = o;
    }
}

// ---------------------------------------------------------------------------
// CSR build: zero counts -> histogram -> scan -> scatter
// ---------------------------------------------------------------------------
__global__ void zero_cnt_kernel(int* cnt, int n) {
    int i = blockIdx.x * blockDim.x + threadIdx.x;
    if (i < n) cnt[i] = 0;
}

__global__ void hist_kernel(const int* __restrict__ dst, int* cnt, int E) {
    int i = blockIdx.x * blockDim.x + threadIdx.x;
    if (i < E) atomicAdd(&cnt[dst[i]], 1);
}

// single block, 1024 threads, 10 elems/thread, warp-shuffle scan
__global__ __launch_bounds__(1024) void scan_kernel(const int* __restrict__ cnt,
                                                    int* rowptr, int* off, int n) {
    constexpr int PER = 10;   // 1024*10 >= NN
    int tid = threadIdx.x;
    int lane = tid & 31, w = tid >> 5;
    int base = tid * PER;

    int local[PER];
    int s = 0;
#pragma unroll
    for (int i = 0; i < PER; i++) {
        int idx = base + i;
        int v = (idx < n) ? cnt[idx] : 0;
        local[i] = v;
        s += v;
    }
    // warp inclusive scan of per-thread sums
    int cs = s;
#pragma unroll
    for (int d = 1; d < 32; d <<= 1) {
        int t = __shfl_up_sync(0xFFFFFFFFu, cs, d);
        if (lane >= d) cs += t;
    }
    __shared__ int wsum[32];
    if (lane == 31) wsum[w] = cs;
    __syncthreads();
    if (w == 0) {
        int v = wsum[lane];
#pragma unroll
        for (int d = 1; d < 32; d <<= 1) {
            int t = __shfl_up_sync(0xFFFFFFFFu, v, d);
            if (lane >= d) v += t;
        }
        wsum[lane] = v;
    }
    __syncthreads();
    int warpbase = (w == 0) ? 0 : wsum[w - 1];
    int run = warpbase + cs - s;     // exclusive prefix for this thread
#pragma unroll
    for (int i = 0; i < PER; i++) {
        int idx = base + i;
        if (idx < n) {
            off[idx] = run;
            rowptr[idx + 1] = run + local[i];
            run += local[i];
        }
    }
    if (tid == 0) rowptr[0] = 0;
}

__global__ void scatter_kernel(const int* __restrict__ src, const int* __restrict__ dst,
                               const float* __restrict__ vals,
                               int* off, int* es, float* ev, int E) {
    int i = blockIdx.x * blockDim.x + threadIdx.x;
    if (i < E) {
        int p = atomicAdd(&off[dst[i]], 1);
        es[p] = src[i];
        ev[p] = vals[i];
    }
}

// ---------------------------------------------------------------------------
// Tensor-core GEMM: H = fp16( X @ [W1|W2|W3] ), wmma m16n16k16, fp32 acc.
// Block: 256 thr = 8 warps (4 m x 2 n). Tile: BM=128, BN=128, BK=64.
// Warp tile: 32 x 64. Grid: (6, ceil(M/128)).
// ---------------------------------------------------------------------------
constexpr int GBM = 128;
constexpr int GBN = 128;
constexpr int GBK = 64;
constexpr int APADH = 72;    // half-stride for As (144B, 16B multiple)
constexpr int BPADH = 136;   // half-stride for Bs (272B, 16B multiple)

__global__ __launch_bounds__(256) void gemm_wmma(
    const __half* __restrict__ xh,
    const __half* __restrict__ wh,
    __half* __restrict__ H, int M)
{
    __shared__ alignas(16) __half As[GBM][APADH];
    __shared__ alignas(16) __half Bs[GBK][BPADH];

    const int n0 = blockIdx.x * GBN;       // over concat width 768
    const int m0 = blockIdx.y * GBM;
    const int which = n0 >> 8;
    const int wc0 = n0 & 255;
    const __half* Wp = wh + (size_t)which * WSZ;

    const int tid = threadIdx.x;
    const int wid = tid >> 5;
    const int warp_m = wid >> 1;           // 0..3 -> 32 rows each
    const int warp_n = wid & 1;            // 0..1 -> 64 cols each

    wmma::fragment<wmma::accumulator, 16, 16, 16, float> cf[2][4];
#pragma unroll
    for (int i = 0; i < 2; i++)
#pragma unroll
        for (int j = 0; j < 4; j++) wmma::fill_fragment(cf[i][j], 0.f);

    for (int k0 = 0; k0 < 256; k0 += GBK) {
        // load A tile: 128 rows x 64 halfs = 1024 uint4, 4 per thread
#pragma unroll
        for (int l = 0; l < 4; l++) {
            int s   = tid + l * 256;       // 0..1023
            int row = s >> 3;              // 0..127
            int c4  = s & 7;               // uint4 col (8 halfs each)
            int gm  = m0 + row;
            uint4 v = make_uint4(0u, 0u, 0u, 0u);
            if (gm < M)
                v = *reinterpret_cast<const uint4*>(xh + (size_t)gm * 256 + k0 + c4 * 8);
            *reinterpret_cast<uint4*>(&As[row][c4 * 8]) = v;
        }
        // load B tile: 64 k-rows x 128 halfs = 1024 uint4
#pragma unroll
        for (int l = 0; l < 4; l++) {
            int s  = tid + l * 256;
            int kr = s >> 4;               // 0..63
            int c4 = s & 15;               // uint4 col
            uint4 v = *reinterpret_cast<const uint4*>(
                Wp + (size_t)(k0 + kr) * 256 + wc0 + c4 * 8);
            *reinterpret_cast<uint4*>(&Bs[kr][c4 * 8]) = v;
        }
        __syncthreads();

#pragma unroll
        for (int kk = 0; kk < GBK; kk += 16) {
            wmma::fragment<wmma::matrix_a, 16, 16, 16, __half, wmma::row_major> af[2];
            wmma::fragment<wmma::matrix_b, 16, 16, 16, __half, wmma::row_major> bf[4];
#pragma unroll
            for (int mi = 0; mi < 2; mi++)
                wmma::load_matrix_sync(af[mi], &As[warp_m * 32 + mi * 16][kk], APADH);
#pragma unroll
            for (int ni = 0; ni < 4; ni++)
                wmma::load_matrix_sync(bf[ni], &Bs[kk][warp_n * 64 + ni * 16], BPADH);
#pragma unroll
            for (int mi = 0; mi < 2; mi++)
#pragma unroll
                for (int ni = 0; ni < 4; ni++)
                    wmma::mma_sync(cf[mi][ni], af[mi], bf[ni], cf[mi][ni]);
        }
        __syncthreads();
    }

    __half* Hout = H + (size_t)which * NF;
#pragma unroll
    for (int mi = 0; mi < 2; mi++) {
        int gm = m0 + warp_m * 32 + mi * 16;
        if (gm < M) {   // M % 16 == 0 -> whole fragment valid or out
#pragma unroll
            for (int ni = 0; ni < 4; ni++) {
                wmma::fragment<wmma::accumulator, 16, 16, 16, __half> ch;
#pragma unroll
                for (int e = 0; e < ch.num_elements; e++)
                    ch.x[e] = __float2half(cf[mi][ni].x[e]);
                wmma::store_matrix_sync(
                    Hout + (size_t)gm * 256 + wc0 + warp_n * 64 + ni * 16,
                    ch, 256, wmma::mem_row_major);
            }
        }
    }
}

// ---------------------------------------------------------------------------
// Horner SpMM pass: r = A @ gin (+ addin[row]); store fp16 (or relu(r/3) fp32).
// Warp per destination row. Lane owns halfs [8*lane, 8*lane+8) = one uint4.
// 4-edge batching for MLP=4 on the 512B row gathers.
// ---------------------------------------------------------------------------
__device__ __forceinline__ void acc_row(float* acc, uint4 r, float v) {
    float2 f0 = h2f(r.x), f1 = h2f(r.y), f2 = h2f(r.z), f3 = h2f(r.w);
    acc[0] = fmaf(v, f0.x, acc[0]); acc[1] = fmaf(v, f0.y, acc[1]);
    acc[2] = fmaf(v, f1.x, acc[2]); acc[3] = fmaf(v, f1.y, acc[3]);
    acc[4] = fmaf(v, f2.x, acc[4]); acc[5] = fmaf(v, f2.y, acc[5]);
    acc[6] = fmaf(v, f3.x, acc[6]); acc[7] = fmaf(v, f3.y, acc[7]);
}

template <bool ADD, bool FINAL>
__global__ __launch_bounds__(256) void spmm_pass(
    const int* __restrict__ rowptr, const int* __restrict__ es,
    const float* __restrict__ ev,
    const __half* __restrict__ gin,
    const __half* __restrict__ addin,
    __half* __restrict__ hout,
    float* __restrict__ fout, int n)
{
    int row = blockIdx.x * 8 + (threadIdx.x >> 5);
    if (row >= n) return;
    int lane = threadIdx.x & 31;
    int beg = rowptr[row], end = rowptr[row + 1];

    const uint4* base = reinterpret_cast<const uint4*>(gin);   // 32 uint4 per row

    float acc[8] = {0, 0, 0, 0, 0, 0, 0, 0};

    int e = beg;
    for (; e + 3 < end; e += 4) {
        int   s0 = __ldg(es + e),     s1 = __ldg(es + e + 1);
        int   s2 = __ldg(es + e + 2), s3 = __ldg(es + e + 3);
        float v0 = __ldg(ev + e),     v1 = __ldg(ev + e + 1);
        float v2 = __ldg(ev + e + 2), v3 = __ldg(ev + e + 3);
        uint4 r0 = __ldg(base + (size_t)s0 * 32 + lane);
        uint4 r1 = __ldg(base + (size_t)s1 * 32 + lane);
        uint4 r2 = __ldg(base + (size_t)s2 * 32 + lane);
        uint4 r3 = __ldg(base + (size_t)s3 * 32 + lane);
        acc_row(acc, r0, v0);
        acc_row(acc, r1, v1);
        acc_row(acc, r2, v2);
        acc_row(acc, r3, v3);
    }
    for (; e < end; e++) {
        int   s = __ldg(es + e);
        float v = __ldg(ev + e);
        uint4 r = __ldg(base + (size_t)s * 32 + lane);
        acc_row(acc, r, v);
    }

    if (ADD) {
        uint4 q = __ldg(reinterpret_cast<const uint4*>(addin) + (size_t)row * 32 + lane);
        float2 f0 = h2f(q.x), f1 = h2f(q.y), f2 = h2f(q.z), f3 = h2f(q.w);
        acc[0] += f0.x; acc[1] += f0.y; acc[2] += f1.x; acc[3] += f1.y;
        acc[4] += f2.x; acc[5] += f2.y; acc[6] += f3.x; acc[7] += f3.y;
    }

    if (FINAL) {
        const float inv3 = 1.0f / 3.0f;
        float4 r0, r1;
        r0.x = fmaxf(acc[0], 0.f) * inv3; r0.y = fmaxf(acc[1], 0.f) * inv3;
        r0.z = fmaxf(acc[2], 0.f) * inv3; r0.w = fmaxf(acc[3], 0.f) * inv3;
        r1.x = fmaxf(acc[4], 0.f) * inv3; r1.y = fmaxf(acc[5], 0.f) * inv3;
        r1.z = fmaxf(acc[6], 0.f) * inv3; r1.w = fmaxf(acc[7], 0.f) * inv3;
        float4* op = reinterpret_cast<float4*>(fout + (size_t)row * 256 + lane * 8);
        op[0] = r0; op[1] = r1;
    } else {
        uint4 o;
        o.x = f2h(acc[0], acc[1]);
        o.y = f2h(acc[2], acc[3]);
        o.z = f2h(acc[4], acc[5]);
        o.w = f2h(acc[6], acc[7]);
        *(reinterpret_cast<uint4*>(hout) + (size_t)row * 32 + lane) = o;
    }
}

// ---------------------------------------------------------------------------
// Launch
// ---------------------------------------------------------------------------
extern "C" void kernel_launch(void* const* d_in, const int* in_sizes, int n_in,
                              void* d_out, int out_size)
{
    const float* x    = (const float*)d_in[0];
    const float* vals = (const float*)d_in[1];
    const float* W1   = (const float*)d_in[2];
    const float* W2   = (const float*)d_in[3];
    const float* W3   = (const float*)d_in[4];
    const int*   src  = (const int*)d_in[5];
    const int*   dst  = (const int*)d_in[6];

    const int M = in_sizes[0] / F;   // nodes
    const int E = in_sizes[1];       // edges

    __half* h;     cudaGetSymbolAddress((void**)&h,      g_h);
    __half* sbuf;  cudaGetSymbolAddress((void**)&sbuf,   g_s);
    __half* xh;    cudaGetSymbolAddress((void**)&xh,     g_xh);
    __half* wh;    cudaGetSymbolAddress((void**)&wh,     g_wh);
    int*   cnt;    cudaGetSymbolAddress((void**)&cnt,    g_cnt);
    int*   rowptr; cudaGetSymbolAddress((void**)&rowptr, g_rowptr);
    int*   off;    cudaGetSymbolAddress((void**)&off,    g_off);
    int*   es;     cudaGetSymbolAddress((void**)&es,     g_es);
    float* ev;     cudaGetSymbolAddress((void**)&ev,     g_ev);

    __half* h1 = h;
    __half* h2 = h + (size_t)NF;
    __half* h3 = h + (size_t)2 * NF;
    __half* s1 = sbuf;
    __half* s2 = sbuf + (size_t)NF;

    // --- CSR build ---
    zero_cnt_kernel<<<(M + 255) / 256, 256>>>(cnt, M);
    hist_kernel<<<(E + 255) / 256, 256>>>(dst, cnt, E);
    scan_kernel<<<1, 1024>>>(cnt, rowptr, off, M);
    scatter_kernel<<<(E + 255) / 256, 256>>>(src, dst, vals, off, es, ev, E);

    // --- fp16 converts ---
    conv_kernel<<<1024, 256>>>((const float4*)x, (uint2*)xh, M * F / 4);
    conv_kernel<<<128, 256>>>((const float4*)W1, (uint2*)wh,                WSZ / 4);
    conv_kernel<<<128, 256>>>((const float4*)W2, (uint2*)(wh + WSZ),        WSZ / 4);
    conv_kernel<<<128, 256>>>((const float4*)W3, (uint2*)(wh + 2 * WSZ),    WSZ / 4);

    // --- GEMM: H = fp16(X @ [W1|W2|W3]) via wmma ---
    {
        dim3 grid(768 / GBN, (M + GBM - 1) / GBM);
        gemm_wmma<<<grid, 256>>>(xh, wh, h, M);
    }

    // --- Horner SpMM chain: out = relu( A@(h1 + A@(h2 + A@h3)) / 3 ) ---
    const int rows_blocks = (M + 7) / 8;
    // s1 = A@h3 + h2
    spmm_pass<true, false><<<rows_blocks, 256>>>(rowptr, es, ev, h3, h2, s1, nullptr, M);
    // s2 = A@s1 + h1
    spmm_pass<true, false><<<rows_blocks, 256>>>(rowptr, es, ev, s1, h1, s2, nullptr, M);
    // out = relu(A@s2 / 3)
    spmm_pass<false, true><<<rows_blocks, 256>>>(rowptr, es, ev, s2, nullptr, nullptr,
                                                 (float*)d_out, M);
}

// round 8
// speedup vs baseline: 4.3442x; 1.0361x over previous
#include <cuda_runtime.h>
#include <cuda_fp16.h>
#include <mma.h>
#include <cstdint>

using namespace nvcuda;

// Problem constants (fixed-shape problem)
constexpr int NN   = 10000;         // nodes
constexpr int F    = 256;           // feature dim
constexpr int NF   = NN * F;        // elems per matrix
constexpr int EMAX = 320000;        // edges

// Scratch (__device__ globals; no allocation allowed)
__device__ __half g_h[3 * NF];      // H1|H2|H3 = fp16(X@W1..3)
__device__ __half g_s[2 * NF];      // s1, s2 intermediates (fp16)
__device__ int    g_cnt[NN];
__device__ int    g_rowptr[NN + 1];
__device__ int    g_off[NN];
__device__ int2   g_epack[EMAX];    // CSR-ordered (src, __float_as_int(val))

// ---------------------------------------------------------------------------
// fp16 helpers
// ---------------------------------------------------------------------------
__device__ __forceinline__ float2 h2f(unsigned u) {
    __half2 h = *reinterpret_cast<__half2*>(&u);
    return __half22float2(h);
}
__device__ __forceinline__ unsigned f2h(float a, float b) {
    __half2 h = __floats2half2_rn(a, b);
    return *reinterpret_cast<unsigned*>(&h);
}

// ---------------------------------------------------------------------------
// CSR build: zero counts -> histogram -> scan -> scatter
// ---------------------------------------------------------------------------
__global__ void zero_cnt_kernel(int* cnt, int n) {
    int i = blockIdx.x * blockDim.x + threadIdx.x;
    if (i < n) cnt[i] = 0;
}

__global__ void hist_kernel(const int* __restrict__ dst, int* cnt, int E) {
    int i = blockIdx.x * blockDim.x + threadIdx.x;
    if (i < E) atomicAdd(&cnt[dst[i]], 1);
}

// single block, 1024 threads, 10 elems/thread, warp-shuffle scan
__global__ __launch_bounds__(1024) void scan_kernel(const int* __restrict__ cnt,
                                                    int* rowptr, int* off, int n) {
    constexpr int PER = 10;   // 1024*10 >= NN
    int tid = threadIdx.x;
    int lane = tid & 31, w = tid >> 5;
    int base = tid * PER;

    int local[PER];
    int s = 0;
#pragma unroll
    for (int i = 0; i < PER; i++) {
        int idx = base + i;
        int v = (idx < n) ? cnt[idx] : 0;
        local[i] = v;
        s += v;
    }
    int cs = s;
#pragma unroll
    for (int d = 1; d < 32; d <<= 1) {
        int t = __shfl_up_sync(0xFFFFFFFFu, cs, d);
        if (lane >= d) cs += t;
    }
    __shared__ int wsum[32];
    if (lane == 31) wsum[w] = cs;
    __syncthreads();
    if (w == 0) {
        int v = wsum[lane];
#pragma unroll
        for (int d = 1; d < 32; d <<= 1) {
            int t = __shfl_up_sync(0xFFFFFFFFu, v, d);
            if (lane >= d) v += t;
        }
        wsum[lane] = v;
    }
    __syncthreads();
    int warpbase = (w == 0) ? 0 : wsum[w - 1];
    int run = warpbase + cs - s;     // exclusive prefix for this thread
#pragma unroll
    for (int i = 0; i < PER; i++) {
        int idx = base + i;
        if (idx < n) {
            off[idx] = run;
            rowptr[idx + 1] = run + local[i];
            run += local[i];
        }
    }
    if (tid == 0) rowptr[0] = 0;
}

__global__ void scatter_kernel(const int* __restrict__ src, const int* __restrict__ dst,
                               const float* __restrict__ vals,
                               int* off, int2* epack, int E) {
    int i = blockIdx.x * blockDim.x + threadIdx.x;
    if (i < E) {
        int p = atomicAdd(&off[dst[i]], 1);
        epack[p] = make_int2(src[i], __float_as_int(vals[i]));
    }
}

// ---------------------------------------------------------------------------
// Tensor-core GEMM with inline fp32->fp16 conversion in the staging path.
// H = fp16( X @ [W1|W2|W3] ), wmma m16n16k16, fp32 acc.
// Block: 256 thr = 8 warps (4 m x 2 n). Tile: BM=128, BN=128, BK=64.
// Grid: (6, ceil(M/128)).
// ---------------------------------------------------------------------------
constexpr int GBM = 128;
constexpr int GBN = 128;
constexpr int GBK = 64;
constexpr int APADH = 72;    // half-stride for As (144B)
constexpr int BPADH = 136;   // half-stride for Bs (272B)

__global__ __launch_bounds__(256) void gemm_wmma(
    const float* __restrict__ x,
    const float* __restrict__ W1,
    const float* __restrict__ W2,
    const float* __restrict__ W3,
    __half* __restrict__ H, int M)
{
    __shared__ alignas(16) __half As[GBM][APADH];
    __shared__ alignas(16) __half Bs[GBK][BPADH];

    const int n0 = blockIdx.x * GBN;       // over concat width 768
    const int m0 = blockIdx.y * GBM;
    const int which = n0 >> 8;
    const int wc0 = n0 & 255;
    const float* Wp = (which == 0) ? W1 : (which == 1) ? W2 : W3;

    const int tid = threadIdx.x;
    const int wid = tid >> 5;
    const int warp_m = wid >> 1;           // 0..3 -> 32 rows each
    const int warp_n = wid & 1;            // 0..1 -> 64 cols each

    wmma::fragment<wmma::accumulator, 16, 16, 16, float> cf[2][4];
#pragma unroll
    for (int i = 0; i < 2; i++)
#pragma unroll
        for (int j = 0; j < 4; j++) wmma::fill_fragment(cf[i][j], 0.f);

    for (int k0 = 0; k0 < 256; k0 += GBK) {
        // A tile: 128 rows x 64 floats = 2048 float4 slots, 8 per thread.
        // Convert to fp16 pairs, store uint2 (8B) into As.
#pragma unroll
        for (int l = 0; l < 8; l++) {
            int s   = tid + l * 256;       // 0..2047
            int row = s >> 4;              // 0..127
            int c   = s & 15;              // float4 col (4 floats)
            int gm  = m0 + row;
            float4 v = make_float4(0.f, 0.f, 0.f, 0.f);
            if (gm < M)
                v = *reinterpret_cast<const float4*>(x + (size_t)gm * 256 + k0 + c * 4);
            uint2 o;
            o.x = f2h(v.x, v.y);
            o.y = f2h(v.z, v.w);
            *reinterpret_cast<uint2*>(&As[row][c * 4]) = o;
        }
        // B tile: 64 k-rows x 128 floats = 2048 float4 slots
#pragma unroll
        for (int l = 0; l < 8; l++) {
            int s  = tid + l * 256;
            int kr = s >> 5;               // 0..63
            int nc = s & 31;               // float4 col
            float4 v = *reinterpret_cast<const float4*>(
                Wp + (size_t)(k0 + kr) * 256 + wc0 + nc * 4);
            uint2 o;
            o.x = f2h(v.x, v.y);
            o.y = f2h(v.z, v.w);
            *reinterpret_cast<uint2*>(&Bs[kr][nc * 4]) = o;
        }
        __syncthreads();

#pragma unroll
        for (int kk = 0; kk < GBK; kk += 16) {
            wmma::fragment<wmma::matrix_a, 16, 16, 16, __half, wmma::row_major> af[2];
            wmma::fragment<wmma::matrix_b, 16, 16, 16, __half, wmma::row_major> bf[4];
#pragma unroll
            for (int mi = 0; mi < 2; mi++)
                wmma::load_matrix_sync(af[mi], &As[warp_m * 32 + mi * 16][kk], APADH);
#pragma unroll
            for (int ni = 0; ni < 4; ni++)
                wmma::load_matrix_sync(bf[ni], &Bs[kk][warp_n * 64 + ni * 16], BPADH);
#pragma unroll
            for (int mi = 0; mi < 2; mi++)
#pragma unroll
                for (int ni = 0; ni < 4; ni++)
                    wmma::mma_sync(cf[mi][ni], af[mi], bf[ni], cf[mi][ni]);
        }
        __syncthreads();
    }

    __half* Hout = H + (size_t)which * NF;
#pragma unroll
    for (int mi = 0; mi < 2; mi++) {
        int gm = m0 + warp_m * 32 + mi * 16;
        if (gm < M) {   // M % 16 == 0 -> whole fragment valid or out
#pragma unroll
            for (int ni = 0; ni < 4; ni++) {
                wmma::fragment<wmma::accumulator, 16, 16, 16, __half> ch;
#pragma unroll
                for (int e = 0; e < ch.num_elements; e++)
                    ch.x[e] = __float2half(cf[mi][ni].x[e]);
                wmma::store_matrix_sync(
                    Hout + (size_t)gm * 256 + wc0 + warp_n * 64 + ni * 16,
                    ch, 256, wmma::mem_row_major);
            }
        }
    }
}

// ---------------------------------------------------------------------------
// Horner SpMM pass: r = A @ gin (+ addin[row]); store fp16 (or relu(r/3) fp32).
// Warp per destination row. Lane owns halfs [8*lane, 8*lane+8) = one uint4.
// 4-edge batching (MLP=4 on the 512B row gathers). Packed int2 edge records.
// ---------------------------------------------------------------------------
__device__ __forceinline__ void acc_row(float* acc, uint4 r, float v) {
    float2 f0 = h2f(r.x), f1 = h2f(r.y), f2 = h2f(r.z), f3 = h2f(r.w);
    acc[0] = fmaf(v, f0.x, acc[0]); acc[1] = fmaf(v, f0.y, acc[1]);
    acc[2] = fmaf(v, f1.x, acc[2]); acc[3] = fmaf(v, f1.y, acc[3]);
    acc[4] = fmaf(v, f2.x, acc[4]); acc[5] = fmaf(v, f2.y, acc[5]);
    acc[6] = fmaf(v, f3.x, acc[6]); acc[7] = fmaf(v, f3.y, acc[7]);
}

template <bool ADD, bool FINAL>
__global__ __launch_bounds__(256) void spmm_pass(
    const int* __restrict__ rowptr, const int2* __restrict__ epack,
    const __half* __restrict__ gin,
    const __half* __restrict__ addin,
    __half* __restrict__ hout,
    float* __restrict__ fout, int n)
{
    int row = blockIdx.x * 8 + (threadIdx.x >> 5);
    if (row >= n) return;
    int lane = threadIdx.x & 31;
    int beg = rowptr[row], end = rowptr[row + 1];

    const uint4* base = reinterpret_cast<const uint4*>(gin);   // 32 uint4 per row

    float acc[8] = {0, 0, 0, 0, 0, 0, 0, 0};

    int e = beg;
    for (; e + 3 < end; e += 4) {
        int2 p0 = __ldg(epack + e),     p1 = __ldg(epack + e + 1);
        int2 p2 = __ldg(epack + e + 2), p3 = __ldg(epack + e + 3);
        uint4 r0 = __ldg(base + (size_t)p0.x * 32 + lane);
        uint4 r1 = __ldg(base + (size_t)p1.x * 32 + lane);
        uint4 r2 = __ldg(base + (size_t)p2.x * 32 + lane);
        uint4 r3 = __ldg(base + (size_t)p3.x * 32 + lane);
        acc_row(acc, r0, __int_as_float(p0.y));
        acc_row(acc, r1, __int_as_float(p1.y));
        acc_row(acc, r2, __int_as_float(p2.y));
        acc_row(acc, r3, __int_as_float(p3.y));
    }
    for (; e < end; e++) {
        int2 p = __ldg(epack + e);
        uint4 r = __ldg(base + (size_t)p.x * 32 + lane);
        acc_row(acc, r, __int_as_float(p.y));
    }

    if (ADD) {
        uint4 q = __ldg(reinterpret_cast<const uint4*>(addin) + (size_t)row * 32 + lane);
        float2 f0 = h2f(q.x), f1 = h2f(q.y), f2 = h2f(q.z), f3 = h2f(q.w);
        acc[0] += f0.x; acc[1] += f0.y; acc[2] += f1.x; acc[3] += f1.y;
        acc[4] += f2.x; acc[5] += f2.y; acc[6] += f3.x; acc[7] += f3.y;
    }

    if (FINAL) {
        const float inv3 = 1.0f / 3.0f;
        float4 r0, r1;
        r0.x = fmaxf(acc[0], 0.f) * inv3; r0.y = fmaxf(acc[1], 0.f) * inv3;
        r0.z = fmaxf(acc[2], 0.f) * inv3; r0.w = fmaxf(acc[3], 0.f) * inv3;
        r1.x = fmaxf(acc[4], 0.f) * inv3; r1.y = fmaxf(acc[5], 0.f) * inv3;
        r1.z = fmaxf(acc[6], 0.f) * inv3; r1.w = fmaxf(acc[7], 0.f) * inv3;
        float4* op = reinterpret_cast<float4*>(fout + (size_t)row * 256 + lane * 8);
        op[0] = r0; op[1] = r1;
    } else {
        uint4 o;
        o.x = f2h(acc[0], acc[1]);
        o.y = f2h(acc[2], acc[3]);
        o.z = f2h(acc[4], acc[5]);
        o.w = f2h(acc[6], acc[7]);
        *(reinterpret_cast<uint4*>(hout) + (size_t)row * 32 + lane) = o;
    }
}

// ---------------------------------------------------------------------------
// Launch
// ---------------------------------------------------------------------------
extern "C" void kernel_launch(void* const* d_in, const int* in_sizes, int n_in,
                              void* d_out, int out_size)
{
    const float* x    = (const float*)d_in[0];
    const float* vals = (const float*)d_in[1];
    const float* W1   = (const float*)d_in[2];
    const float* W2   = (const float*)d_in[3];
    const float* W3   = (const float*)d_in[4];
    const int*   src  = (const int*)d_in[5];
    const int*   dst  = (const int*)d_in[6];

    const int M = in_sizes[0] / F;   // nodes
    const int E = in_sizes[1];       // edges

    __half* h;     cudaGetSymbolAddress((void**)&h,      g_h);
    __half* sbuf;  cudaGetSymbolAddress((void**)&sbuf,   g_s);
    int*   cnt;    cudaGetSymbolAddress((void**)&cnt,    g_cnt);
    int*   rowptr; cudaGetSymbolAddress((void**)&rowptr, g_rowptr);
    int*   off;    cudaGetSymbolAddress((void**)&off,    g_off);
    int2*  epack;  cudaGetSymbolAddress((void**)&epack,  g_epack);

    __half* h1 = h;
    __half* h2 = h + (size_t)NF;
    __half* h3 = h + (size_t)2 * NF;
    __half* s1 = sbuf;
    __half* s2 = sbuf + (size_t)NF;

    // --- CSR build ---
    zero_cnt_kernel<<<(M + 255) / 256, 256>>>(cnt, M);
    hist_kernel<<<(E + 255) / 256, 256>>>(dst, cnt, E);
    scan_kernel<<<1, 1024>>>(cnt, rowptr, off, M);
    scatter_kernel<<<(E + 255) / 256, 256>>>(src, dst, vals, off, epack, E);

    // --- GEMM: H = fp16(X @ [W1|W2|W3]) with inline conversion ---
    {
        dim3 grid(768 / GBN, (M + GBM - 1) / GBM);
        gemm_wmma<<<grid, 256>>>(x, W1, W2, W3, h, M);
    }

    // --- Horner SpMM chain: out = relu( A@(h1 + A@(h2 + A@h3)) / 3 ) ---
    const int rows_blocks = (M + 7) / 8;
    // s1 = A@h3 + h2
    spmm_pass<true, false><<<rows_blocks, 256>>>(rowptr, epack, h3, h2, s1, nullptr, M);
    // s2 = A@s1 + h1
    spmm_pass<true, false><<<rows_blocks, 256>>>(rowptr, epack, s1, h1, s2, nullptr, M);
    // out = relu(A@s2 / 3)
    spmm_pass<false, true><<<rows_blocks, 256>>>(rowptr, epack, s2, nullptr, nullptr,
                                                 (float*)d_out, M);
}

// round 9
// speedup vs baseline: 4.6734x; 1.0758x over previous
#include <cuda_runtime.h>
#include <cuda_fp16.h>
#include <mma.h>
#include <cstdint>

using namespace nvcuda;

// Problem constants (fixed-shape problem)
constexpr int NN   = 10000;         // nodes
constexpr int F    = 256;           // feature dim
constexpr int NF   = NN * F;        // elems per matrix
constexpr int EMAX = 320000;        // edges

// Scratch (__device__ globals; no allocation allowed)
__device__ __half g_h[3 * NF];      // H1|H2|H3 = fp16(X@W1..3)
__device__ __half g_s[2 * NF];      // s1, s2 intermediates (fp16)
__device__ int    g_cnt[NN];
__device__ int    g_rowptr[NN + 1];
__device__ int    g_off[NN];
__device__ int2   g_epack[EMAX];    // CSR-ordered (src, __float_as_int(val))

// ---------------------------------------------------------------------------
// fp16 helpers
// ---------------------------------------------------------------------------
__device__ __forceinline__ float2 h2f(unsigned u) {
    __half2 h = *reinterpret_cast<__half2*>(&u);
    return __half22float2(h);
}
__device__ __forceinline__ unsigned f2h(float a, float b) {
    __half2 h = __floats2half2_rn(a, b);
    return *reinterpret_cast<unsigned*>(&h);
}

// ---------------------------------------------------------------------------
// CSR build: histogram -> scan -> scatter  (cnt zeroed via memset node)
// ---------------------------------------------------------------------------
__global__ void hist_kernel(const int* __restrict__ dst, int* cnt, int E) {
    int i = blockIdx.x * blockDim.x + threadIdx.x;
    if (i < E) atomicAdd(&cnt[dst[i]], 1);
}

// single block, 1024 threads, 10 elems/thread, warp-shuffle scan
__global__ __launch_bounds__(1024) void scan_kernel(const int* __restrict__ cnt,
                                                    int* rowptr, int* off, int n) {
    constexpr int PER = 10;   // 1024*10 >= NN
    int tid = threadIdx.x;
    int lane = tid & 31, w = tid >> 5;
    int base = tid * PER;

    int local[PER];
    int s = 0;
#pragma unroll
    for (int i = 0; i < PER; i++) {
        int idx = base + i;
        int v = (idx < n) ? cnt[idx] : 0;
        local[i] = v;
        s += v;
    }
    int cs = s;
#pragma unroll
    for (int d = 1; d < 32; d <<= 1) {
        int t = __shfl_up_sync(0xFFFFFFFFu, cs, d);
        if (lane >= d) cs += t;
    }
    __shared__ int wsum[32];
    if (lane == 31) wsum[w] = cs;
    __syncthreads();
    if (w == 0) {
        int v = wsum[lane];
#pragma unroll
        for (int d = 1; d < 32; d <<= 1) {
            int t = __shfl_up_sync(0xFFFFFFFFu, v, d);
            if (lane >= d) v += t;
        }
        wsum[lane] = v;
    }
    __syncthreads();
    int warpbase = (w == 0) ? 0 : wsum[w - 1];
    int run = warpbase + cs - s;     // exclusive prefix for this thread
#pragma unroll
    for (int i = 0; i < PER; i++) {
        int idx = base + i;
        if (idx < n) {
            off[idx] = run;
            rowptr[idx + 1] = run + local[i];
            run += local[i];
        }
    }
    if (tid == 0) rowptr[0] = 0;
}

__global__ void scatter_kernel(const int* __restrict__ src, const int* __restrict__ dst,
                               const float* __restrict__ vals,
                               int* off, int2* epack, int E) {
    int i = blockIdx.x * blockDim.x + threadIdx.x;
    if (i < E) {
        int p = atomicAdd(&off[dst[i]], 1);
        epack[p] = make_int2(src[i], __float_as_int(vals[i]));
    }
}

// ---------------------------------------------------------------------------
// Tensor-core GEMM with inline fp32->fp16 conversion in the staging path.
// H = fp16( X @ [W1|W2|W3] ), wmma m16n16k16, fp32 acc.
// Block: 256 thr = 8 warps (4 m x 2 n). Tile: BM=128, BN=128, BK=64.
// Grid: (6, ceil(M/128)).
// ---------------------------------------------------------------------------
constexpr int GBM = 128;
constexpr int GBN = 128;
constexpr int GBK = 64;
constexpr int APADH = 72;    // half-stride for As (144B)
constexpr int BPADH = 136;   // half-stride for Bs (272B)

__global__ __launch_bounds__(256) void gemm_wmma(
    const float* __restrict__ x,
    const float* __restrict__ W1,
    const float* __restrict__ W2,
    const float* __restrict__ W3,
    __half* __restrict__ H, int M)
{
    __shared__ alignas(16) __half As[GBM][APADH];
    __shared__ alignas(16) __half Bs[GBK][BPADH];

    const int n0 = blockIdx.x * GBN;       // over concat width 768
    const int m0 = blockIdx.y * GBM;
    const int which = n0 >> 8;
    const int wc0 = n0 & 255;
    const float* Wp = (which == 0) ? W1 : (which == 1) ? W2 : W3;

    const int tid = threadIdx.x;
    const int wid = tid >> 5;
    const int warp_m = wid >> 1;           // 0..3 -> 32 rows each
    const int warp_n = wid & 1;            // 0..1 -> 64 cols each

    wmma::fragment<wmma::accumulator, 16, 16, 16, float> cf[2][4];
#pragma unroll
    for (int i = 0; i < 2; i++)
#pragma unroll
        for (int j = 0; j < 4; j++) wmma::fill_fragment(cf[i][j], 0.f);

    for (int k0 = 0; k0 < 256; k0 += GBK) {
        // A tile: 128 rows x 64 floats = 2048 float4 slots, 8 per thread.
#pragma unroll
        for (int l = 0; l < 8; l++) {
            int s   = tid + l * 256;       // 0..2047
            int row = s >> 4;              // 0..127
            int c   = s & 15;              // float4 col (4 floats)
            int gm  = m0 + row;
            float4 v = make_float4(0.f, 0.f, 0.f, 0.f);
            if (gm < M)
                v = *reinterpret_cast<const float4*>(x + (size_t)gm * 256 + k0 + c * 4);
            uint2 o;
            o.x = f2h(v.x, v.y);
            o.y = f2h(v.z, v.w);
            *reinterpret_cast<uint2*>(&As[row][c * 4]) = o;
        }
        // B tile: 64 k-rows x 128 floats = 2048 float4 slots
#pragma unroll
        for (int l = 0; l < 8; l++) {
            int s  = tid + l * 256;
            int kr = s >> 5;               // 0..63
            int nc = s & 31;               // float4 col
            float4 v = *reinterpret_cast<const float4*>(
                Wp + (size_t)(k0 + kr) * 256 + wc0 + nc * 4);
            uint2 o;
            o.x = f2h(v.x, v.y);
            o.y = f2h(v.z, v.w);
            *reinterpret_cast<uint2*>(&Bs[kr][nc * 4]) = o;
        }
        __syncthreads();

#pragma unroll
        for (int kk = 0; kk < GBK; kk += 16) {
            wmma::fragment<wmma::matrix_a, 16, 16, 16, __half, wmma::row_major> af[2];
            wmma::fragment<wmma::matrix_b, 16, 16, 16, __half, wmma::row_major> bf[4];
#pragma unroll
            for (int mi = 0; mi < 2; mi++)
                wmma::load_matrix_sync(af[mi], &As[warp_m * 32 + mi * 16][kk], APADH);
#pragma unroll
            for (int ni = 0; ni < 4; ni++)
                wmma::load_matrix_sync(bf[ni], &Bs[kk][warp_n * 64 + ni * 16], BPADH);
#pragma unroll
            for (int mi = 0; mi < 2; mi++)
#pragma unroll
                for (int ni = 0; ni < 4; ni++)
                    wmma::mma_sync(cf[mi][ni], af[mi], bf[ni], cf[mi][ni]);
        }
        __syncthreads();
    }

    __half* Hout = H + (size_t)which * NF;
#pragma unroll
    for (int mi = 0; mi < 2; mi++) {
        int gm = m0 + warp_m * 32 + mi * 16;
        if (gm < M) {   // M % 16 == 0 -> whole fragment valid or out
#pragma unroll
            for (int ni = 0; ni < 4; ni++) {
                wmma::fragment<wmma::accumulator, 16, 16, 16, __half> ch;
#pragma unroll
                for (int e = 0; e < ch.num_elements; e++)
                    ch.x[e] = __float2half(cf[mi][ni].x[e]);
                wmma::store_matrix_sync(
                    Hout + (size_t)gm * 256 + wc0 + warp_n * 64 + ni * 16,
                    ch, 256, wmma::mem_row_major);
            }
        }
    }
}

// ---------------------------------------------------------------------------
// Horner SpMM pass: r = A @ gin (+ addin[row]); store fp16 (or relu(r/3) fp32).
// Warp per destination row. Lane owns halfs [8*lane, 8*lane+8) = one uint4.
// 4-edge batching (MLP=4 on the 512B row gathers). Packed int2 edge records.
// ---------------------------------------------------------------------------
__device__ __forceinline__ void acc_row(float* acc, uint4 r, float v) {
    float2 f0 = h2f(r.x), f1 = h2f(r.y), f2 = h2f(r.z), f3 = h2f(r.w);
    acc[0] = fmaf(v, f0.x, acc[0]); acc[1] = fmaf(v, f0.y, acc[1]);
    acc[2] = fmaf(v, f1.x, acc[2]); acc[3] = fmaf(v, f1.y, acc[3]);
    acc[4] = fmaf(v, f2.x, acc[4]); acc[5] = fmaf(v, f2.y, acc[5]);
    acc[6] = fmaf(v, f3.x, acc[6]); acc[7] = fmaf(v, f3.y, acc[7]);
}

template <bool ADD, bool FINAL>
__global__ __launch_bounds__(256) void spmm_pass(
    const int* __restrict__ rowptr, const int2* __restrict__ epack,
    const __half* __restrict__ gin,
    const __half* __restrict__ addin,
    __half* __restrict__ hout,
    float* __restrict__ fout, int n)
{
    int row = blockIdx.x * 8 + (threadIdx.x >> 5);
    if (row >= n) return;
    int lane = threadIdx.x & 31;
    int beg = rowptr[row], end = rowptr[row + 1];

    const uint4* base = reinterpret_cast<const uint4*>(gin);   // 32 uint4 per row

    float acc[8] = {0, 0, 0, 0, 0, 0, 0, 0};

    int e = beg;
    for (; e + 3 < end; e += 4) {
        int2 p0 = __ldg(epack + e),     p1 = __ldg(epack + e + 1);
        int2 p2 = __ldg(epack + e + 2), p3 = __ldg(epack + e + 3);
        uint4 r0 = __ldg(base + (size_t)p0.x * 32 + lane);
        uint4 r1 = __ldg(base + (size_t)p1.x * 32 + lane);
        uint4 r2 = __ldg(base + (size_t)p2.x * 32 + lane);
        uint4 r3 = __ldg(base + (size_t)p3.x * 32 + lane);
        acc_row(acc, r0, __int_as_float(p0.y));
        acc_row(acc, r1, __int_as_float(p1.y));
        acc_row(acc, r2, __int_as_float(p2.y));
        acc_row(acc, r3, __int_as_float(p3.y));
    }
    for (; e < end; e++) {
        int2 p = __ldg(epack + e);
        uint4 r = __ldg(base + (size_t)p.x * 32 + lane);
        acc_row(acc, r, __int_as_float(p.y));
    }

    if (ADD) {
        uint4 q = __ldg(reinterpret_cast<const uint4*>(addin) + (size_t)row * 32 + lane);
        float2 f0 = h2f(q.x), f1 = h2f(q.y), f2 = h2f(q.z), f3 = h2f(q.w);
        acc[0] += f0.x; acc[1] += f0.y; acc[2] += f1.x; acc[3] += f1.y;
        acc[4] += f2.x; acc[5] += f2.y; acc[6] += f3.x; acc[7] += f3.y;
    }

    if (FINAL) {
        const float inv3 = 1.0f / 3.0f;
        float4 r0, r1;
        r0.x = fmaxf(acc[0], 0.f) * inv3; r0.y = fmaxf(acc[1], 0.f) * inv3;
        r0.z = fmaxf(acc[2], 0.f) * inv3; r0.w = fmaxf(acc[3], 0.f) * inv3;
        r1.x = fmaxf(acc[4], 0.f) * inv3; r1.y = fmaxf(acc[5], 0.f) * inv3;
        r1.z = fmaxf(acc[6], 0.f) * inv3; r1.w = fmaxf(acc[7], 0.f) * inv3;
        float4* op = reinterpret_cast<float4*>(fout + (size_t)row * 256 + lane * 8);
        op[0] = r0; op[1] = r1;
    } else {
        uint4 o;
        o.x = f2h(acc[0], acc[1]);
        o.y = f2h(acc[2], acc[3]);
        o.z = f2h(acc[4], acc[5]);
        o.w = f2h(acc[6], acc[7]);
        *(reinterpret_cast<uint4*>(hout) + (size_t)row * 32 + lane) = o;
    }
}

// ---------------------------------------------------------------------------
// Launch — fork/join: GEMM on side stream concurrent with CSR build.
// Streams/events are host-side resources created once (device work is
// identical on every call; graph capture sees the same fork-join DAG).
// ---------------------------------------------------------------------------
static cudaStream_t g_s2 = nullptr;
static cudaEvent_t  g_evFork = nullptr, g_evJoin = nullptr;

extern "C" void kernel_launch(void* const* d_in, const int* in_sizes, int n_in,
                              void* d_out, int out_size)
{
    const float* x    = (const float*)d_in[0];
    const float* vals = (const float*)d_in[1];
    const float* W1   = (const float*)d_in[2];
    const float* W2   = (const float*)d_in[3];
    const float* W3   = (const float*)d_in[4];
    const int*   src  = (const int*)d_in[5];
    const int*   dst  = (const int*)d_in[6];

    const int M = in_sizes[0] / F;   // nodes
    const int E = in_sizes[1];       // edges

    __half* h;     cudaGetSymbolAddress((void**)&h,      g_h);
    __half* sbuf;  cudaGetSymbolAddress((void**)&sbuf,   g_s);
    int*   cnt;    cudaGetSymbolAddress((void**)&cnt,    g_cnt);
    int*   rowptr; cudaGetSymbolAddress((void**)&rowptr, g_rowptr);
    int*   off;    cudaGetSymbolAddress((void**)&off,    g_off);
    int2*  epack;  cudaGetSymbolAddress((void**)&epack,  g_epack);

    __half* h1 = h;
    __half* h2 = h + (size_t)NF;
    __half* h3 = h + (size_t)2 * NF;
    __half* s1 = sbuf;
    __half* s2 = sbuf + (size_t)NF;

    if (!g_s2) {
        cudaStreamCreateWithFlags(&g_s2, cudaStreamNonBlocking);
        cudaEventCreateWithFlags(&g_evFork, cudaEventDisableTiming);
        cudaEventCreateWithFlags(&g_evJoin, cudaEventDisableTiming);
    }

    // --- fork: GEMM on side stream ---
    cudaEventRecord(g_evFork, 0);
    cudaStreamWaitEvent(g_s2, g_evFork, 0);
    {
        dim3 grid(768 / GBN, (M + GBM - 1) / GBM);
        gemm_wmma<<<grid, 256, 0, g_s2>>>(x, W1, W2, W3, h, M);
    }

    // --- CSR build on main stream (concurrent with GEMM) ---
    cudaMemsetAsync(cnt, 0, (size_t)M * sizeof(int), 0);
    hist_kernel<<<(E + 255) / 256, 256>>>(dst, cnt, E);
    scan_kernel<<<1, 1024>>>(cnt, rowptr, off, M);
    scatter_kernel<<<(E + 255) / 256, 256>>>(src, dst, vals, off, epack, E);

    // --- join ---
    cudaEventRecord(g_evJoin, g_s2);
    cudaStreamWaitEvent(0, g_evJoin, 0);

    // --- Horner SpMM chain: out = relu( A@(h1 + A@(h2 + A@h3)) / 3 ) ---
    const int rows_blocks = (M + 7) / 8;
    // s1 = A@h3 + h2
    spmm_pass<true, false><<<rows_blocks, 256>>>(rowptr, epack, h3, h2, s1, nullptr, M);
    // s2 = A@s1 + h1
    spmm_pass<true, false><<<rows_blocks, 256>>>(rowptr, epack, s1, h1, s2, nullptr, M);
    // out = relu(A@s2 / 3)
    spmm_pass<false, true><<<rows_blocks, 256>>>(rowptr, epack, s2, nullptr, nullptr,
                                                 (float*)d_out, M);
}

// round 11
// speedup vs baseline: 4.7845x; 1.0238x over previous
#include <cuda_runtime.h>
#include <cuda_fp16.h>
#include <mma.h>
#include <cstdint>

using namespace nvcuda;

// Problem constants (fixed-shape problem)
constexpr int NN   = 10000;         // nodes
constexpr int F    = 256;           // feature dim
constexpr int NF   = NN * F;        // elems per matrix
constexpr int EMAX = 320000;        // edges
constexpr int WSZ  = 65536;         // 256*256 per W

// Scratch (__device__ globals; no allocation allowed)
__device__ __half g_h[3 * NF];      // H1|H2|H3 = fp16(X@W1..3)
__device__ __half g_s[2 * NF];      // s1, s2 intermediates (fp16)
__device__ __half g_xh[NF];         // fp16 X
__device__ __half g_wh[3 * WSZ];    // fp16 W1|W2|W3
__device__ int    g_cnt[NN];
__device__ int    g_rowptr[NN + 1];
__device__ int    g_off[NN];
__device__ int2   g_epack[EMAX];    // CSR-ordered (src, __float_as_int(val))

// ---------------------------------------------------------------------------
// fp16 helpers
// ---------------------------------------------------------------------------
__device__ __forceinline__ float2 h2f(unsigned u) {
    __half2 h = *reinterpret_cast<__half2*>(&u);
    return __half22float2(h);
}
__device__ __forceinline__ unsigned f2h(float a, float b) {
    __half2 h = __floats2half2_rn(a, b);
    return *reinterpret_cast<unsigned*>(&h);
}

// ---------------------------------------------------------------------------
// Fused fp32->fp16 convert: X and W1..W3 in one launch (index-partitioned)
// ---------------------------------------------------------------------------
__global__ void conv_all_kernel(const float4* __restrict__ x,
                                const float4* __restrict__ W1,
                                const float4* __restrict__ W2,
                                const float4* __restrict__ W3,
                                uint2* __restrict__ xh, uint2* __restrict__ wh,
                                int n_x4)
{
    const int n_w4 = WSZ / 4;
    const int total = n_x4 + 3 * n_w4;
    int i = blockIdx.x * blockDim.x + threadIdx.x;
    int stride = gridDim.x * blockDim.x;
    for (; i < total; i += stride) {
        float4 v;
        uint2* out;
        if (i < n_x4) {
            v = __ldg(x + i);
            out = xh + i;
        } else {
            int j = i - n_x4;
            int which = j / n_w4;
            int k = j - which * n_w4;
            const float4* Wp = (which == 0) ? W1 : (which == 1) ? W2 : W3;
            v = __ldg(Wp + k);
            out = wh + (size_t)which * (WSZ / 4) + k;
        }
        uint2 o;
        o.x = f2h(v.x, v.y);
        o.y = f2h(v.z, v.w);
        *out = o;
    }
}

// ---------------------------------------------------------------------------
// CSR build: histogram -> scan -> scatter  (4 edges/thread for MLP)
// ---------------------------------------------------------------------------
__global__ void hist_kernel(const int* __restrict__ dst, int* cnt, int E) {
    int i0 = (blockIdx.x * blockDim.x + threadIdx.x) * 4;
#pragma unroll
    for (int j = 0; j < 4; j++) {
        int i = i0 + j;
        if (i < E) atomicAdd(&cnt[__ldg(dst + i)], 1);
    }
}

// single block, 1024 threads, 10 elems/thread, warp-shuffle scan
__global__ __launch_bounds__(1024) void scan_kernel(const int* __restrict__ cnt,
                                                    int* rowptr, int* off, int n) {
    constexpr int PER = 10;   // 1024*10 >= NN
    int tid = threadIdx.x;
    int lane = tid & 31, w = tid >> 5;
    int base = tid * PER;

    int local[PER];
    int s = 0;
#pragma unroll
    for (int i = 0; i < PER; i++) {
        int idx = base + i;
        int v = (idx < n) ? cnt[idx] : 0;
        local[i] = v;
        s += v;
    }
    int cs = s;
#pragma unroll
    for (int d = 1; d < 32; d <<= 1) {
        int t = __shfl_up_sync(0xFFFFFFFFu, cs, d);
        if (lane >= d) cs += t;
    }
    __shared__ int wsum[32];
    if (lane == 31) wsum[w] = cs;
    __syncthreads();
    if (w == 0) {
        int v = wsum[lane];
#pragma unroll
        for (int d = 1; d < 32; d <<= 1) {
            int t = __shfl_up_sync(0xFFFFFFFFu, v, d);
            if (lane >= d) v += t;
        }
        wsum[lane] = v;
    }
    __syncthreads();
    int warpbase = (w == 0) ? 0 : wsum[w - 1];
    int run = warpbase + cs - s;     // exclusive prefix for this thread
#pragma unroll
    for (int i = 0; i < PER; i++) {
        int idx = base + i;
        if (idx < n) {
            off[idx] = run;
            rowptr[idx + 1] = run + local[i];
            run += local[i];
        }
    }
    if (tid == 0) rowptr[0] = 0;
}

__global__ void scatter_kernel(const int* __restrict__ src, const int* __restrict__ dst,
                               const float* __restrict__ vals,
                               int* off, int2* epack, int E) {
    int i0 = (blockIdx.x * blockDim.x + threadIdx.x) * 4;
    if (i0 + 3 < E) {
        int  d0 = __ldg(dst + i0),     d1 = __ldg(dst + i0 + 1);
        int  d2 = __ldg(dst + i0 + 2), d3 = __ldg(dst + i0 + 3);
        int  s0 = __ldg(src + i0),     s1 = __ldg(src + i0 + 1);
        int  s2 = __ldg(src + i0 + 2), s3 = __ldg(src + i0 + 3);
        float v0 = __ldg(vals + i0),     v1 = __ldg(vals + i0 + 1);
        float v2 = __ldg(vals + i0 + 2), v3 = __ldg(vals + i0 + 3);
        int p0 = atomicAdd(&off[d0], 1);
        int p1 = atomicAdd(&off[d1], 1);
        int p2 = atomicAdd(&off[d2], 1);
        int p3 = atomicAdd(&off[d3], 1);
        epack[p0] = make_int2(s0, __float_as_int(v0));
        epack[p1] = make_int2(s1, __float_as_int(v1));
        epack[p2] = make_int2(s2, __float_as_int(v2));
        epack[p3] = make_int2(s3, __float_as_int(v3));
    } else {
        for (int i = i0; i < E; i++) {
            int p = atomicAdd(&off[__ldg(dst + i)], 1);
            epack[p] = make_int2(__ldg(src + i), __float_as_int(__ldg(vals + i)));
        }
    }
}

// ---------------------------------------------------------------------------
// Tensor-core GEMM (fp16-staged): H = fp16( Xh @ [W1|W2|W3]h ).
// wmma m16n16k16, fp32 acc. Block 256 = 8 warps (4m x 2n).
// Tile BM=128, BN=128, BK=64. Grid: (6, ceil(M/128)).
// ---------------------------------------------------------------------------
constexpr int GBM = 128;
constexpr int GBN = 128;
constexpr int GBK = 64;
constexpr int APADH = 72;    // half-stride for As (144B)
constexpr int BPADH = 136;   // half-stride for Bs (272B)

__global__ __launch_bounds__(256) void gemm_wmma(
    const __half* __restrict__ xh,
    const __half* __restrict__ wh,
    __half* __restrict__ H, int M)
{
    __shared__ alignas(16) __half As[GBM][APADH];
    __shared__ alignas(16) __half Bs[GBK][BPADH];

    const int n0 = blockIdx.x * GBN;       // over concat width 768
    const int m0 = blockIdx.y * GBM;
    const int which = n0 >> 8;
    const int wc0 = n0 & 255;
    const __half* Wp = wh + (size_t)which * WSZ;

    const int tid = threadIdx.x;
    const int wid = tid >> 5;
    const int warp_m = wid >> 1;           // 0..3 -> 32 rows each
    const int warp_n = wid & 1;            // 0..1 -> 64 cols each

    wmma::fragment<wmma::accumulator, 16, 16, 16, float> cf[2][4];
#pragma unroll
    for (int i = 0; i < 2; i++)
#pragma unroll
        for (int j = 0; j < 4; j++) wmma::fill_fragment(cf[i][j], 0.f);

    for (int k0 = 0; k0 < 256; k0 += GBK) {
        // A tile: 128 rows x 64 halfs = 1024 uint4, 4 per thread
#pragma unroll
        for (int l = 0; l < 4; l++) {
            int s   = tid + l * 256;       // 0..1023
            int row = s >> 3;              // 0..127
            int c4  = s & 7;               // uint4 col (8 halfs)
            int gm  = m0 + row;
            uint4 v = make_uint4(0u, 0u, 0u, 0u);
            if (gm < M)
                v = *reinterpret_cast<const uint4*>(xh + (size_t)gm * 256 + k0 + c4 * 8);
            *reinterpret_cast<uint4*>(&As[row][c4 * 8]) = v;
        }
        // B tile: 64 k-rows x 128 halfs = 1024 uint4
#pragma unroll
        for (int l = 0; l < 4; l++) {
            int s  = tid + l * 256;
            int kr = s >> 4;               // 0..63
            int c4 = s & 15;               // uint4 col
            uint4 v = *reinterpret_cast<const uint4*>(
                Wp + (size_t)(k0 + kr) * 256 + wc0 + c4 * 8);
            *reinterpret_cast<uint4*>(&Bs[kr][c4 * 8]) = v;
        }
        __syncthreads();

#pragma unroll
        for (int kk = 0; kk < GBK; kk += 16) {
            wmma::fragment<wmma::matrix_a, 16, 16, 16, __half, wmma::row_major> af[2];
            wmma::fragment<wmma::matrix_b, 16, 16, 16, __half, wmma::row_major> bf[4];
#pragma unroll
            for (int mi = 0; mi < 2; mi++)
                wmma::load_matrix_sync(af[mi], &As[warp_m * 32 + mi * 16][kk], APADH);
#pragma unroll
            for (int ni = 0; ni < 4; ni++)
                wmma::load_matrix_sync(bf[ni], &Bs[kk][warp_n * 64 + ni * 16], BPADH);
#pragma unroll
            for (int mi = 0; mi < 2; mi++)
#pragma unroll
                for (int ni = 0; ni < 4; ni++)
                    wmma::mma_sync(cf[mi][ni], af[mi], bf[ni], cf[mi][ni]);
        }
        __syncthreads();
    }

    __half* Hout = H + (size_t)which * NF;
#pragma unroll
    for (int mi = 0; mi < 2; mi++) {
        int gm = m0 + warp_m * 32 + mi * 16;
        if (gm < M) {   // M % 16 == 0 -> whole fragment valid or out
#pragma unroll
            for (int ni = 0; ni < 4; ni++) {
                wmma::fragment<wmma::accumulator, 16, 16, 16, __half> ch;
#pragma unroll
                for (int e = 0; e < ch.num_elements; e++)
                    ch.x[e] = __float2half(cf[mi][ni].x[e]);
                wmma::store_matrix_sync(
                    Hout + (size_t)gm * 256 + wc0 + warp_n * 64 + ni * 16,
                    ch, 256, wmma::mem_row_major);
            }
        }
    }
}

// ---------------------------------------------------------------------------
// Horner SpMM pass: r = A @ gin (+ addin[row]); store fp16 (or relu(r/3) fp32).
// Warp per destination row. Lane owns halfs [8*lane, 8*lane+8) = one uint4.
// 4-edge batching (MLP=4 on the 512B row gathers). Packed int2 edge records.
// ---------------------------------------------------------------------------
__device__ __forceinline__ void acc_row(float* acc, uint4 r, float v) {
    float2 f0 = h2f(r.x), f1 = h2f(r.y), f2 = h2f(r.z), f3 = h2f(r.w);
    acc[0] = fmaf(v, f0.x, acc[0]); acc[1] = fmaf(v, f0.y, acc[1]);
    acc[2] = fmaf(v, f1.x, acc[2]); acc[3] = fmaf(v, f1.y, acc[3]);
    acc[4] = fmaf(v, f2.x, acc[4]); acc[5] = fmaf(v, f2.y, acc[5]);
    acc[6] = fmaf(v, f3.x, acc[6]); acc[7] = fmaf(v, f3.y, acc[7]);
}

template <bool ADD, bool FINAL>
__global__ __launch_bounds__(256) void spmm_pass(
    const int* __restrict__ rowptr, const int2* __restrict__ epack,
    const __half* __restrict__ gin,
    const __half* __restrict__ addin,
    __half* __restrict__ hout,
    float* __restrict__ fout, int n)
{
    int row = blockIdx.x * 8 + (threadIdx.x >> 5);
    if (row >= n) return;
    int lane = threadIdx.x & 31;
    int beg = rowptr[row], end = rowptr[row + 1];

    const uint4* base = reinterpret_cast<const uint4*>(gin);   // 32 uint4 per row

    float acc[8] = {0, 0, 0, 0, 0, 0, 0, 0};

    int e = beg;
    for (; e + 3 < end; e += 4) {
        int2 p0 = __ldg(epack + e),     p1 = __ldg(epack + e + 1);
        int2 p2 = __ldg(epack + e + 2), p3 = __ldg(epack + e + 3);
        uint4 r0 = __ldg(base + (size_t)p0.x * 32 + lane);
        uint4 r1 = __ldg(base + (size_t)p1.x * 32 + lane);
        uint4 r2 = __ldg(base + (size_t)p2.x * 32 + lane);
        uint4 r3 = __ldg(base + (size_t)p3.x * 32 + lane);
        acc_row(acc, r0, __int_as_float(p0.y));
        acc_row(acc, r1, __int_as_float(p1.y));
        acc_row(acc, r2, __int_as_float(p2.y));
        acc_row(acc, r3, __int_as_float(p3.y));
    }
    for (; e < end; e++) {
        int2 p = __ldg(epack + e);
        uint4 r = __ldg(base + (size_t)p.x * 32 + lane);
        acc_row(acc, r, __int_as_float(p.y));
    }

    if (ADD) {
        uint4 q = __ldg(reinterpret_cast<const uint4*>(addin) + (size_t)row * 32 + lane);
        float2 f0 = h2f(q.x), f1 = h2f(q.y), f2 = h2f(q.z), f3 = h2f(q.w);
        acc[0] += f0.x; acc[1] += f0.y; acc[2] += f1.x; acc[3] += f1.y;
        acc[4] += f2.x; acc[5] += f2.y; acc[6] += f3.x; acc[7] += f3.y;
    }

    if (FINAL) {
        const float inv3 = 1.0f / 3.0f;
        float4 r0, r1;
        r0.x = fmaxf(acc[0], 0.f) * inv3; r0.y = fmaxf(acc[1], 0.f) * inv3;
        r0.z = fmaxf(acc[2], 0.f) * inv3; r0.w = fmaxf(acc[3], 0.f) * inv3;
        r1.x = fmaxf(acc[4], 0.f) * inv3; r1.y = fmaxf(acc[5], 0.f) * inv3;
        r1.z = fmaxf(acc[6], 0.f) * inv3; r1.w = fmaxf(acc[7], 0.f) * inv3;
        float4* op = reinterpret_cast<float4*>(fout + (size_t)row * 256 + lane * 8);
        op[0] = r0; op[1] = r1;
    } else {
        uint4 o;
        o.x = f2h(acc[0], acc[1]);
        o.y = f2h(acc[2], acc[3]);
        o.z = f2h(acc[4], acc[5]);
        o.w = f2h(acc[6], acc[7]);
        *(reinterpret_cast<uint4*>(hout) + (size_t)row * 32 + lane) = o;
    }
}

// ---------------------------------------------------------------------------
// Launch — fork/join: (convert + GEMM) on side stream || CSR build on main.
// ---------------------------------------------------------------------------
static cudaStream_t g_s2 = nullptr;
static cudaEvent_t  g_evFork = nullptr, g_evJoin = nullptr;

extern "C" void kernel_launch(void* const* d_in, const int* in_sizes, int n_in,
                              void* d_out, int out_size)
{
    const float* x    = (const float*)d_in[0];
    const float* vals = (const float*)d_in[1];
    const float* W1   = (const float*)d_in[2];
    const float* W2   = (const float*)d_in[3];
    const float* W3   = (const float*)d_in[4];
    const int*   src  = (const int*)d_in[5];
    const int*   dst  = (const int*)d_in[6];

    const int M = in_sizes[0] / F;   // nodes
    const int E = in_sizes[1];       // edges

    __half* h;     cudaGetSymbolAddress((void**)&h,      g_h);
    __half* sbuf;  cudaGetSymbolAddress((void**)&sbuf,   g_s);
    __half* xh;    cudaGetSymbolAddress((void**)&xh,     g_xh);
    __half* wh;    cudaGetSymbolAddress((void**)&wh,     g_wh);
    int*   cnt;    cudaGetSymbolAddress((void**)&cnt,    g_cnt);
    int*   rowptr; cudaGetSymbolAddress((void**)&rowptr, g_rowptr);
    int*   off;    cudaGetSymbolAddress((void**)&off,    g_off);
    int2*  epack;  cudaGetSymbolAddress((void**)&epack,  g_epack);

    __half* h1 = h;
    __half* h2 = h + (size_t)NF;
    __half* h3 = h + (size_t)2 * NF;
    __half* s1 = sbuf;
    __half* s2 = sbuf + (size_t)NF;

    if (!g_s2) {
        cudaStreamCreateWithFlags(&g_s2, cudaStreamNonBlocking);
        cudaEventCreateWithFlags(&g_evFork, cudaEventDisableTiming);
        cudaEventCreateWithFlags(&g_evJoin, cudaEventDisableTiming);
    }

    // --- fork: convert + GEMM on side stream ---
    cudaEventRecord(g_evFork, 0);
    cudaStreamWaitEvent(g_s2, g_evFork, 0);
    conv_all_kernel<<<1024, 256, 0, g_s2>>>(
        (const float4*)x, (const float4*)W1, (const float4*)W2, (const float4*)W3,
        (uint2*)xh, (uint2*)wh, M * F / 4);
    {
        dim3 grid(768 / GBN, (M + GBM - 1) / GBM);
        gemm_wmma<<<grid, 256, 0, g_s2>>>(xh, wh, h, M);
    }

    // --- CSR build on main stream (concurrent with GEMM) ---
    cudaMemsetAsync(cnt, 0, (size_t)M * sizeof(int), 0);
    hist_kernel<<<(E / 4 + 255) / 256, 256>>>(dst, cnt, E);
    scan_kernel<<<1, 1024>>>(cnt, rowptr, off, M);
    scatter_kernel<<<(E / 4 + 255) / 256, 256>>>(src, dst, vals, off, epack, E);

    // --- join ---
    cudaEventRecord(g_evJoin, g_s2);
    cudaStreamWaitEvent(0, g_evJoin, 0);

    // --- Horner SpMM chain: out = relu( A@(h1 + A@(h2 + A@h3)) / 3 ) ---
    const int rows_blocks = (M + 7) / 8;
    // s1 = A@h3 + h2
    spmm_pass<true, false><<<rows_blocks, 256>>>(rowptr, epack, h3, h2, s1, nullptr, M);
    // s2 = A@s1 + h1
    spmm_pass<true, false><<<rows_blocks, 256>>>(rowptr, epack, s1, h1, s2, nullptr, M);
    // out = relu(A@s2 / 3)
    spmm_pass<false, true><<<rows_blocks, 256>>>(rowptr, epack, s2, nullptr, nullptr,
                                                 (float*)d_out, M);
}

// round 12
// speedup vs baseline: 5.1519x; 1.0768x over previous
#include <cuda_runtime.h>
#include <cuda_fp16.h>
#include <mma.h>
#include <cstdint>

using namespace nvcuda;

// Problem constants (fixed-shape problem)
constexpr int NN   = 10000;         // nodes
constexpr int F    = 256;           // feature dim
constexpr int NF   = NN * F;        // elems per matrix
constexpr int EMAX = 320000;        // edges
constexpr int WSZ  = 65536;         // 256*256 per W
constexpr int SCAN_BLK   = 1024;
constexpr int SCAN_NBLK  = (NN + SCAN_BLK - 1) / SCAN_BLK;   // 10

// Scratch (__device__ globals; no allocation allowed)
__device__ __half g_h[3 * NF];      // H1|H2|H3 = fp16(X@W1..3)
__device__ __half g_s[2 * NF];      // s1, s2 intermediates (fp16)
__device__ __half g_xh[NF];         // fp16 X
__device__ __half g_wh[3 * WSZ];    // fp16 W1|W2|W3
__device__ int    g_cnt[NN];
__device__ int    g_rowptr[NN + 1];
__device__ int    g_off[NN];
__device__ int    g_bsum[SCAN_NBLK];
__device__ int2   g_epack[EMAX];    // CSR-ordered (src, __float_as_int(val))

// ---------------------------------------------------------------------------
// fp16 helpers
// ---------------------------------------------------------------------------
__device__ __forceinline__ float2 h2f(unsigned u) {
    __half2 h = *reinterpret_cast<__half2*>(&u);
    return __half22float2(h);
}
__device__ __forceinline__ unsigned f2h(float a, float b) {
    __half2 h = __floats2half2_rn(a, b);
    return *reinterpret_cast<unsigned*>(&h);
}

// ---------------------------------------------------------------------------
// Fused fp32->fp16 convert: X and W1..W3 in one launch (index-partitioned)
// ---------------------------------------------------------------------------
__global__ void conv_all_kernel(const float4* __restrict__ x,
                                const float4* __restrict__ W1,
                                const float4* __restrict__ W2,
                                const float4* __restrict__ W3,
                                uint2* __restrict__ xh, uint2* __restrict__ wh,
                                int n_x4)
{
    const int n_w4 = WSZ / 4;
    const int total = n_x4 + 3 * n_w4;
    int i = blockIdx.x * blockDim.x + threadIdx.x;
    int stride = gridDim.x * blockDim.x;
    for (; i < total; i += stride) {
        float4 v;
        uint2* out;
        if (i < n_x4) {
            v = __ldg(x + i);
            out = xh + i;
        } else {
            int j = i - n_x4;
            int which = j / n_w4;
            int k = j - which * n_w4;
            const float4* Wp = (which == 0) ? W1 : (which == 1) ? W2 : W3;
            v = __ldg(Wp + k);
            out = wh + (size_t)which * (WSZ / 4) + k;
        }
        uint2 o;
        o.x = f2h(v.x, v.y);
        o.y = f2h(v.z, v.w);
        *out = o;
    }
}

// ---------------------------------------------------------------------------
// CSR build: histogram -> 2-kernel coalesced scan -> scatter
// ---------------------------------------------------------------------------
__global__ void hist_kernel(const int* __restrict__ dst, int* cnt, int E) {
    int i0 = (blockIdx.x * blockDim.x + threadIdx.x) * 4;
#pragma unroll
    for (int j = 0; j < 4; j++) {
        int i = i0 + j;
        if (i < E) atomicAdd(&cnt[__ldg(dst + i)], 1);
    }
}

// k1: per-block reduction of cnt chunks -> bsum[b]
__global__ __launch_bounds__(SCAN_BLK) void scan_sum_kernel(
    const int* __restrict__ cnt, int* bsum, int n)
{
    int tid = threadIdx.x;
    int idx = blockIdx.x * SCAN_BLK + tid;
    int v = (idx < n) ? __ldg(cnt + idx) : 0;
    // warp reduce
#pragma unroll
    for (int d = 16; d > 0; d >>= 1)
        v += __shfl_down_sync(0xFFFFFFFFu, v, d);
    __shared__ int ws[32];
    int lane = tid & 31, w = tid >> 5;
    if (lane == 0) ws[w] = v;
    __syncthreads();
    if (w == 0) {
        int t = ws[lane];
#pragma unroll
        for (int d = 16; d > 0; d >>= 1)
            t += __shfl_down_sync(0xFFFFFFFFu, t, d);
        if (lane == 0) bsum[blockIdx.x] = t;
    }
}

// k2: block-local shuffle scan + cross-block prefix from bsum
__global__ __launch_bounds__(SCAN_BLK) void scan_fix_kernel(
    const int* __restrict__ cnt, const int* __restrict__ bsum,
    int* rowptr, int* off, int n)
{
    int tid = threadIdx.x;
    int b   = blockIdx.x;
    int idx = b * SCAN_BLK + tid;
    int lane = tid & 31, w = tid >> 5;

    // prefix over block sums (<= SCAN_NBLK values, trivial)
    int blockpre = 0;
    for (int i = 0; i < b; i++) blockpre += __ldg(bsum + i);

    int v = (idx < n) ? __ldg(cnt + idx) : 0;
    // warp inclusive scan
    int cs = v;
#pragma unroll
    for (int d = 1; d < 32; d <<= 1) {
        int t = __shfl_up_sync(0xFFFFFFFFu, cs, d);
        if (lane >= d) cs += t;
    }
    __shared__ int ws[32];
    if (lane == 31) ws[w] = cs;
    __syncthreads();
    if (w == 0) {
        int t = ws[lane];
#pragma unroll
        for (int d = 1; d < 32; d <<= 1) {
            int u = __shfl_up_sync(0xFFFFFFFFu, t, d);
            if (lane >= d) t += u;
        }
        ws[lane] = t;
    }
    __syncthreads();
    int warppre = (w == 0) ? 0 : ws[w - 1];
    int excl = blockpre + warppre + cs - v;   // exclusive prefix for idx

    if (idx < n) {
        off[idx] = excl;
        rowptr[idx + 1] = excl + v;
    }
    if (idx == 0) rowptr[0] = 0;
}

__global__ void scatter_kernel(const int* __restrict__ src, const int* __restrict__ dst,
                               const float* __restrict__ vals,
                               int* off, int2* epack, int E) {
    int i0 = (blockIdx.x * blockDim.x + threadIdx.x) * 4;
    if (i0 + 3 < E) {
        int  d0 = __ldg(dst + i0),     d1 = __ldg(dst + i0 + 1);
        int  d2 = __ldg(dst + i0 + 2), d3 = __ldg(dst + i0 + 3);
        int  s0 = __ldg(src + i0),     s1 = __ldg(src + i0 + 1);
        int  s2 = __ldg(src + i0 + 2), s3 = __ldg(src + i0 + 3);
        float v0 = __ldg(vals + i0),     v1 = __ldg(vals + i0 + 1);
        float v2 = __ldg(vals + i0 + 2), v3 = __ldg(vals + i0 + 3);
        int p0 = atomicAdd(&off[d0], 1);
        int p1 = atomicAdd(&off[d1], 1);
        int p2 = atomicAdd(&off[d2], 1);
        int p3 = atomicAdd(&off[d3], 1);
        epack[p0] = make_int2(s0, __float_as_int(v0));
        epack[p1] = make_int2(s1, __float_as_int(v1));
        epack[p2] = make_int2(s2, __float_as_int(v2));
        epack[p3] = make_int2(s3, __float_as_int(v3));
    } else {
        for (int i = i0; i < E; i++) {
            int p = atomicAdd(&off[__ldg(dst + i)], 1);
            epack[p] = make_int2(__ldg(src + i), __float_as_int(__ldg(vals + i)));
        }
    }
}

// ---------------------------------------------------------------------------
// Tensor-core GEMM (fp16-staged): H = fp16( Xh @ [W1|W2|W3]h ).
// wmma m16n16k16, fp32 acc. Block 256 = 8 warps (4m x 2n).
// Tile BM=128, BN=128, BK=64. Grid: (6, ceil(M/128)).
// ---------------------------------------------------------------------------
constexpr int GBM = 128;
constexpr int GBN = 128;
constexpr int GBK = 64;
constexpr int APADH = 72;    // half-stride for As (144B)
constexpr int BPADH = 136;   // half-stride for Bs (272B)

__global__ __launch_bounds__(256) void gemm_wmma(
    const __half* __restrict__ xh,
    const __half* __restrict__ wh,
    __half* __restrict__ H, int M)
{
    __shared__ alignas(16) __half As[GBM][APADH];
    __shared__ alignas(16) __half Bs[GBK][BPADH];

    const int n0 = blockIdx.x * GBN;       // over concat width 768
    const int m0 = blockIdx.y * GBM;
    const int which = n0 >> 8;
    const int wc0 = n0 & 255;
    const __half* Wp = wh + (size_t)which * WSZ;

    const int tid = threadIdx.x;
    const int wid = tid >> 5;
    const int warp_m = wid >> 1;           // 0..3 -> 32 rows each
    const int warp_n = wid & 1;            // 0..1 -> 64 cols each

    wmma::fragment<wmma::accumulator, 16, 16, 16, float> cf[2][4];
#pragma unroll
    for (int i = 0; i < 2; i++)
#pragma unroll
        for (int j = 0; j < 4; j++) wmma::fill_fragment(cf[i][j], 0.f);

    for (int k0 = 0; k0 < 256; k0 += GBK) {
        // A tile: 128 rows x 64 halfs = 1024 uint4, 4 per thread
#pragma unroll
        for (int l = 0; l < 4; l++) {
            int s   = tid + l * 256;       // 0..1023
            int row = s >> 3;              // 0..127
            int c4  = s & 7;               // uint4 col (8 halfs)
            int gm  = m0 + row;
            uint4 v = make_uint4(0u, 0u, 0u, 0u);
            if (gm < M)
                v = *reinterpret_cast<const uint4*>(xh + (size_t)gm * 256 + k0 + c4 * 8);
            *reinterpret_cast<uint4*>(&As[row][c4 * 8]) = v;
        }
        // B tile: 64 k-rows x 128 halfs = 1024 uint4
#pragma unroll
        for (int l = 0; l < 4; l++) {
            int s  = tid + l * 256;
            int kr = s >> 4;               // 0..63
            int c4 = s & 15;               // uint4 col
            uint4 v = *reinterpret_cast<const uint4*>(
                Wp + (size_t)(k0 + kr) * 256 + wc0 + c4 * 8);
            *reinterpret_cast<uint4*>(&Bs[kr][c4 * 8]) = v;
        }
        __syncthreads();

#pragma unroll
        for (int kk = 0; kk < GBK; kk += 16) {
            wmma::fragment<wmma::matrix_a, 16, 16, 16, __half, wmma::row_major> af[2];
            wmma::fragment<wmma::matrix_b, 16, 16, 16, __half, wmma::row_major> bf[4];
#pragma unroll
            for (int mi = 0; mi < 2; mi++)
                wmma::load_matrix_sync(af[mi], &As[warp_m * 32 + mi * 16][kk], APADH);
#pragma unroll
            for (int ni = 0; ni < 4; ni++)
                wmma::load_matrix_sync(bf[ni], &Bs[kk][warp_n * 64 + ni * 16], BPADH);
#pragma unroll
            for (int mi = 0; mi < 2; mi++)
#pragma unroll
                for (int ni = 0; ni < 4; ni++)
                    wmma::mma_sync(cf[mi][ni], af[mi], bf[ni], cf[mi][ni]);
        }
        __syncthreads();
    }

    __half* Hout = H + (size_t)which * NF;
#pragma unroll
    for (int mi = 0; mi < 2; mi++) {
        int gm = m0 + warp_m * 32 + mi * 16;
        if (gm < M) {   // M % 16 == 0 -> whole fragment valid or out
#pragma unroll
            for (int ni = 0; ni < 4; ni++) {
                wmma::fragment<wmma::accumulator, 16, 16, 16, __half> ch;
#pragma unroll
                for (int e = 0; e < ch.num_elements; e++)
                    ch.x[e] = __float2half(cf[mi][ni].x[e]);
                wmma::store_matrix_sync(
                    Hout + (size_t)gm * 256 + wc0 + warp_n * 64 + ni * 16,
                    ch, 256, wmma::mem_row_major);
            }
        }
    }
}

// ---------------------------------------------------------------------------
// Horner SpMM pass: r = A @ gin (+ addin[row]); store fp16 (or relu(r/3) fp32).
// Warp per destination row. Lane owns halfs [8*lane, 8*lane+8) = one uint4.
// 4-edge batching (MLP=4 on the 512B row gathers). Packed int2 edge records.
// ---------------------------------------------------------------------------
__device__ __forceinline__ void acc_row(float* acc, uint4 r, float v) {
    float2 f0 = h2f(r.x), f1 = h2f(r.y), f2 = h2f(r.z), f3 = h2f(r.w);
    acc[0] = fmaf(v, f0.x, acc[0]); acc[1] = fmaf(v, f0.y, acc[1]);
    acc[2] = fmaf(v, f1.x, acc[2]); acc[3] = fmaf(v, f1.y, acc[3]);
    acc[4] = fmaf(v, f2.x, acc[4]); acc[5] = fmaf(v, f2.y, acc[5]);
    acc[6] = fmaf(v, f3.x, acc[6]); acc[7] = fmaf(v, f3.y, acc[7]);
}

template <bool ADD, bool FINAL>
__global__ __launch_bounds__(256) void spmm_pass(
    const int* __restrict__ rowptr, const int2* __restrict__ epack,
    const __half* __restrict__ gin,
    const __half* __restrict__ addin,
    __half* __restrict__ hout,
    float* __restrict__ fout, int n)
{
    int row = blockIdx.x * 8 + (threadIdx.x >> 5);
    if (row >= n) return;
    int lane = threadIdx.x & 31;
    int beg = rowptr[row], end = rowptr[row + 1];

    const uint4* base = reinterpret_cast<const uint4*>(gin);   // 32 uint4 per row

    float acc[8] = {0, 0, 0, 0, 0, 0, 0, 0};

    int e = beg;
    for (; e + 3 < end; e += 4) {
        int2 p0 = __ldg(epack + e),     p1 = __ldg(epack + e + 1);
        int2 p2 = __ldg(epack + e + 2), p3 = __ldg(epack + e + 3);
        uint4 r0 = __ldg(base + (size_t)p0.x * 32 + lane);
        uint4 r1 = __ldg(base + (size_t)p1.x * 32 + lane);
        uint4 r2 = __ldg(base + (size_t)p2.x * 32 + lane);
        uint4 r3 = __ldg(base + (size_t)p3.x * 32 + lane);
        acc_row(acc, r0, __int_as_float(p0.y));
        acc_row(acc, r1, __int_as_float(p1.y));
        acc_row(acc, r2, __int_as_float(p2.y));
        acc_row(acc, r3, __int_as_float(p3.y));
    }
    for (; e < end; e++) {
        int2 p = __ldg(epack + e);
        uint4 r = __ldg(base + (size_t)p.x * 32 + lane);
        acc_row(acc, r, __int_as_float(p.y));
    }

    if (ADD) {
        uint4 q = __ldg(reinterpret_cast<const uint4*>(addin) + (size_t)row * 32 + lane);
        float2 f0 = h2f(q.x), f1 = h2f(q.y), f2 = h2f(q.z), f3 = h2f(q.w);
        acc[0] += f0.x; acc[1] += f0.y; acc[2] += f1.x; acc[3] += f1.y;
        acc[4] += f2.x; acc[5] += f2.y; acc[6] += f3.x; acc[7] += f3.y;
    }

    if (FINAL) {
        const float inv3 = 1.0f / 3.0f;
        float4 r0, r1;
        r0.x = fmaxf(acc[0], 0.f) * inv3; r0.y = fmaxf(acc[1], 0.f) * inv3;
        r0.z = fmaxf(acc[2], 0.f) * inv3; r0.w = fmaxf(acc[3], 0.f) * inv3;
        r1.x = fmaxf(acc[4], 0.f) * inv3; r1.y = fmaxf(acc[5], 0.f) * inv3;
        r1.z = fmaxf(acc[6], 0.f) * inv3; r1.w = fmaxf(acc[7], 0.f) * inv3;
        float4* op = reinterpret_cast<float4*>(fout + (size_t)row * 256 + lane * 8);
        op[0] = r0; op[1] = r1;
    } else {
        uint4 o;
        o.x = f2h(acc[0], acc[1]);
        o.y = f2h(acc[2], acc[3]);
        o.z = f2h(acc[4], acc[5]);
        o.w = f2h(acc[6], acc[7]);
        *(reinterpret_cast<uint4*>(hout) + (size_t)row * 32 + lane) = o;
    }
}

// ---------------------------------------------------------------------------
// Launch — fork/join: (convert + GEMM) on side stream || CSR build on main.
// ---------------------------------------------------------------------------
static cudaStream_t g_s2 = nullptr;
static cudaEvent_t  g_evFork = nullptr, g_evJoin = nullptr;

extern "C" void kernel_launch(void* const* d_in, const int* in_sizes, int n_in,
                              void* d_out, int out_size)
{
    const float* x    = (const float*)d_in[0];
    const float* vals = (const float*)d_in[1];
    const float* W1   = (const float*)d_in[2];
    const float* W2   = (const float*)d_in[3];
    const float* W3   = (const float*)d_in[4];
    const int*   src  = (const int*)d_in[5];
    const int*   dst  = (const int*)d_in[6];

    const int M = in_sizes[0] / F;   // nodes
    const int E = in_sizes[1];       // edges

    __half* h;     cudaGetSymbolAddress((void**)&h,      g_h);
    __half* sbuf;  cudaGetSymbolAddress((void**)&sbuf,   g_s);
    __half* xh;    cudaGetSymbolAddress((void**)&xh,     g_xh);
    __half* wh;    cudaGetSymbolAddress((void**)&wh,     g_wh);
    int*   cnt;    cudaGetSymbolAddress((void**)&cnt,    g_cnt);
    int*   rowptr; cudaGetSymbolAddress((void**)&rowptr, g_rowptr);
    int*   off;    cudaGetSymbolAddress((void**)&off,    g_off);
    int*   bsum;   cudaGetSymbolAddress((void**)&bsum,   g_bsum);
    int2*  epack;  cudaGetSymbolAddress((void**)&epack,  g_epack);

    __half* h1 = h;
    __half* h2 = h + (size_t)NF;
    __half* h3 = h + (size_t)2 * NF;
    __half* s1 = sbuf;
    __half* s2 = sbuf + (size_t)NF;

    if (!g_s2) {
        cudaStreamCreateWithFlags(&g_s2, cudaStreamNonBlocking);
        cudaEventCreateWithFlags(&g_evFork, cudaEventDisableTiming);
        cudaEventCreateWithFlags(&g_evJoin, cudaEventDisableTiming);
    }

    // --- fork: convert + GEMM on side stream ---
    cudaEventRecord(g_evFork, 0);
    cudaStreamWaitEvent(g_s2, g_evFork, 0);
    conv_all_kernel<<<1024, 256, 0, g_s2>>>(
        (const float4*)x, (const float4*)W1, (const float4*)W2, (const float4*)W3,
        (uint2*)xh, (uint2*)wh, M * F / 4);
    {
        dim3 grid(768 / GBN, (M + GBM - 1) / GBM);
        gemm_wmma<<<grid, 256, 0, g_s2>>>(xh, wh, h, M);
    }

    // --- CSR build on main stream (concurrent with GEMM) ---
    cudaMemsetAsync(cnt, 0, (size_t)M * sizeof(int), 0);
    hist_kernel<<<(E / 4 + 255) / 256, 256>>>(dst, cnt, E);
    {
        int nblk = (M + SCAN_BLK - 1) / SCAN_BLK;
        scan_sum_kernel<<<nblk, SCAN_BLK>>>(cnt, bsum, M);
        scan_fix_kernel<<<nblk, SCAN_BLK>>>(cnt, bsum, rowptr, off, M);
    }
    scatter_kernel<<<(E / 4 + 255) / 256, 256>>>(src, dst, vals, off, epack, E);

    // --- join ---
    cudaEventRecord(g_evJoin, g_s2);
    cudaStreamWaitEvent(0, g_evJoin, 0);

    // --- Horner SpMM chain: out = relu( A@(h1 + A@(h2 + A@h3)) / 3 ) ---
    const int rows_blocks = (M + 7) / 8;
    // s1 = A@h3 + h2
    spmm_pass<true, false><<<rows_blocks, 256>>>(rowptr, epack, h3, h2, s1, nullptr, M);
    // s2 = A@s1 + h1
    spmm_pass<true, false><<<rows_blocks, 256>>>(rowptr, epack, s1, h1, s2, nullptr, M);
    // out = relu(A@s2 / 3)
    spmm_pass<false, true><<<rows_blocks, 256>>>(rowptr, epack, s2, nullptr, nullptr,
                                                 (float*)d_out, M);
}